// round 2
// baseline (speedup 1.0000x reference)
#include <cuda_runtime.h>
#include <stdint.h>

// Problem constants
#define B_ 8
#define N_ 512
#define D_ 768
#define A_ 12
#define E_ 64
#define M_ (B_ * N_)   // 4096

// Scratch (device globals: allocation-free)
__device__ float g_h[B_ * A_ * N_ * E_];     // [b][a][i][e]  12.6 MB
__device__ float g_src[B_ * A_ * N_];
__device__ float g_dst[B_ * A_ * N_];
__device__ float g_att[B_ * N_ * D_];        // [b][i][a*64+e] (attn@h + bias b)
__device__ int   g_adj_int;

// ---------------------------------------------------------------------------
// adj dtype detection: int32 0/1 words => int layout; packed bool bytes give
// words like 0x00010001 which are neither 0 nor 1.
// ---------------------------------------------------------------------------
__global__ void detect_adj_kernel(const int* __restrict__ adj) {
    int ok = 1;
    for (int v = threadIdx.x; v < 1024; v += 32) {
        int w = adj[v];
        if (w != 0 && w != 1) ok = 0;
    }
#pragma unroll
    for (int o = 16; o; o >>= 1) ok &= __shfl_xor_sync(0xffffffffu, ok, o);
    if (threadIdx.x == 0) g_adj_int = ok;
}

// ---------------------------------------------------------------------------
// GEMM-1: h[b,i,a,e] = sum_d feat[b,i,d] * W[a,d,e]
// 4096x768 x 768x768 ; B matrix addressed as W[(n>>6)*768*64 + k*64 + (n&63)]
// 128x128x16 tiles, 256 threads, 8x8 per thread, double-buffered smem.
// ---------------------------------------------------------------------------
__global__ __launch_bounds__(256, 2) void gemm_h_kernel(const float* __restrict__ Af,
                                                        const float* __restrict__ W) {
    __shared__ float As[2][16][128];
    __shared__ float Bs[2][16][128];
    const int tid = threadIdx.x;
    const int m0 = blockIdx.y << 7;
    const int n0 = blockIdx.x << 7;

    const int arow = tid >> 2;
    const int acol = (tid & 3) << 2;
    const float* Ap0 = Af + (m0 + arow) * D_ + acol;
    const float* Ap1 = Ap0 + 64 * D_;

    const int bk = tid >> 5;                 // 0..7
    const int bn = (tid & 31) << 2;          // 0..124
    const int head = (n0 + bn) >> 6;
    const int be = (n0 + bn) & 63;
    const float* Wp0 = W + (head * D_ + bk) * E_ + be;
    const float* Wp1 = Wp0 + 8 * E_;

    float4 pa0 = *(const float4*)Ap0;
    float4 pa1 = *(const float4*)Ap1;
    float4 pb0 = *(const float4*)Wp0;
    float4 pb1 = *(const float4*)Wp1;

    const int txb = (tid & 15) << 3;
    const int tyb = (tid >> 4) << 3;

    float acc[8][8];
#pragma unroll
    for (int i = 0; i < 8; ++i)
#pragma unroll
        for (int j = 0; j < 8; ++j) acc[i][j] = 0.f;

#define STORE_AB1(s) do {                                                     \
    As[s][acol+0][arow] = pa0.x; As[s][acol+1][arow] = pa0.y;                 \
    As[s][acol+2][arow] = pa0.z; As[s][acol+3][arow] = pa0.w;                 \
    As[s][acol+0][arow+64] = pa1.x; As[s][acol+1][arow+64] = pa1.y;           \
    As[s][acol+2][arow+64] = pa1.z; As[s][acol+3][arow+64] = pa1.w;           \
    *(float4*)&Bs[s][bk][bn] = pb0;                                           \
    *(float4*)&Bs[s][bk+8][bn] = pb1; } while (0)

    STORE_AB1(0);
    __syncthreads();

    const int KT = D_ / 16;  // 48
    for (int kt = 0; kt < KT; ++kt) {
        const int s = kt & 1;
        if (kt + 1 < KT) {
            Ap0 += 16; Ap1 += 16;
            Wp0 += 16 * E_; Wp1 += 16 * E_;
            pa0 = *(const float4*)Ap0;
            pa1 = *(const float4*)Ap1;
            pb0 = *(const float4*)Wp0;
            pb1 = *(const float4*)Wp1;
        }
#pragma unroll
        for (int k = 0; k < 16; ++k) {
            alignas(16) float ra[8], rb[8];
            *(float4*)&ra[0] = *(const float4*)&As[s][k][tyb];
            *(float4*)&ra[4] = *(const float4*)&As[s][k][tyb + 4];
            *(float4*)&rb[0] = *(const float4*)&Bs[s][k][txb];
            *(float4*)&rb[4] = *(const float4*)&Bs[s][k][txb + 4];
#pragma unroll
            for (int i = 0; i < 8; ++i)
#pragma unroll
                for (int j = 0; j < 8; ++j)
                    acc[i][j] = fmaf(ra[i], rb[j], acc[i][j]);
        }
        if (kt + 1 < KT) STORE_AB1(s ^ 1);
        __syncthreads();
    }
#undef STORE_AB1

    // epilogue: scatter to g_h[b][a][i][e]
    const int bidx = m0 >> 9;  // block fits in one b (128 < 512)
#pragma unroll
    for (int i = 0; i < 8; ++i) {
        const int m = m0 + tyb + i;
        const int irow = m & (N_ - 1);
#pragma unroll
        for (int jv = 0; jv < 8; jv += 4) {
            const int n = n0 + txb + jv;
            float4 v = make_float4(acc[i][jv], acc[i][jv + 1], acc[i][jv + 2], acc[i][jv + 3]);
            *(float4*)&g_h[(((bidx * A_) + (n >> 6)) * N_ + irow) * E_ + (n & 63)] = v;
        }
    }
}

// ---------------------------------------------------------------------------
// src/dst: warp per (b,a,i) row: tanh(h) . w_src / w_dst
// ---------------------------------------------------------------------------
__global__ void srcdst_kernel(const float* __restrict__ wsrc, const float* __restrict__ wdst) {
    const int warp = (blockIdx.x * blockDim.x + threadIdx.x) >> 5;
    const int lane = threadIdx.x & 31;
    const int a = (warp >> 9) % A_;
    const float* hr = g_h + (size_t)warp * E_;
    float t0 = tanhf(hr[lane]);
    float t1 = tanhf(hr[lane + 32]);
    float s = t0 * __ldg(wsrc + a * E_ + lane) + t1 * __ldg(wsrc + a * E_ + lane + 32);
    float d = t0 * __ldg(wdst + a * E_ + lane) + t1 * __ldg(wdst + a * E_ + lane + 32);
#pragma unroll
    for (int o = 16; o; o >>= 1) {
        s += __shfl_xor_sync(0xffffffffu, s, o);
        d += __shfl_xor_sync(0xffffffffu, d, o);
    }
    if (lane == 0) { g_src[warp] = s; g_dst[warp] = d; }
}

// ---------------------------------------------------------------------------
// Attention: block = (isplit, a, b). h[b,a] tile (128KB) in smem.
// Per row i: logits, masked leaky-relu, softmax, attn @ h -> g_att.
// ---------------------------------------------------------------------------
#define ISPLIT 4
#define ATT_SMEM_FLOATS (N_ * E_ + N_ + N_ + 256 + 16)

__global__ __launch_bounds__(256) void attn_kernel(const void* __restrict__ adjv,
                                                   const float* __restrict__ bbias) {
    extern __shared__ float sm[];
    float* sh_h = sm;                    // 32768
    float* sh_dst = sm + N_ * E_;        // 512
    float* sh_p = sh_dst + N_;           // 512
    float* sh_red = sh_p + N_;           // 256
    float* sh_w = sh_red + 256;          // 16

    const int tid = threadIdx.x;
    const int b = blockIdx.z, a = blockIdx.y;
    const int ba = b * A_ + a;

    const float4* hsrc = (const float4*)(g_h + (size_t)ba * N_ * E_);
    for (int v = tid; v < N_ * E_ / 4; v += 256) ((float4*)sh_h)[v] = hsrc[v];
    sh_dst[tid] = g_dst[ba * N_ + tid];
    sh_dst[tid + 256] = g_dst[ba * N_ + tid + 256];
    __syncthreads();

    const int lane = tid & 31, wid = tid >> 5;
    const int e = tid & 63, jg = tid >> 6;
    const int adj_int = g_adj_int;
    const uint8_t* adj8 = (const uint8_t*)adjv;
    const int* adj32 = (const int*)adjv;

    const int i0 = blockIdx.x * (N_ / ISPLIT);
    for (int i = i0; i < i0 + N_ / ISPLIT; ++i) {
        const float si = __ldg(&g_src[ba * N_ + i]);
        const int rowoff = (b * N_ + i) * N_;
        bool c0, c1;
        if (adj_int) { c0 = adj32[rowoff + tid] != 0; c1 = adj32[rowoff + tid + 256] != 0; }
        else         { c0 = adj8[rowoff + tid] != 0;  c1 = adj8[rowoff + tid + 256] != 0; }
        float l0 = si + sh_dst[tid];
        float l1 = si + sh_dst[tid + 256];
        l0 = l0 >= 0.f ? l0 : 0.2f * l0;
        l1 = l1 >= 0.f ? l1 : 0.2f * l1;
        if (!c0) l0 = -999.f;
        if (!c1) l1 = -999.f;

        float mx = fmaxf(l0, l1);
#pragma unroll
        for (int o = 16; o; o >>= 1) mx = fmaxf(mx, __shfl_xor_sync(0xffffffffu, mx, o));
        if (lane == 0) sh_w[wid] = mx;
        __syncthreads();
        float rmax = sh_w[0];
#pragma unroll
        for (int w = 1; w < 8; ++w) rmax = fmaxf(rmax, sh_w[w]);

        float p0 = __expf(l0 - rmax);
        float p1 = __expf(l1 - rmax);
        sh_p[tid] = p0;
        sh_p[tid + 256] = p1;
        float ssum = p0 + p1;
#pragma unroll
        for (int o = 16; o; o >>= 1) ssum += __shfl_xor_sync(0xffffffffu, ssum, o);
        if (lane == 0) sh_w[8 + wid] = ssum;
        __syncthreads();
        float denom = sh_w[8];
#pragma unroll
        for (int w = 1; w < 8; ++w) denom += sh_w[8 + w];
        const float inv = __fdividef(1.f, denom);

        const float* hp = sh_h + (jg << 7) * E_ + e;
        const float* pp = sh_p + (jg << 7);
        float acc = 0.f;
#pragma unroll 8
        for (int jj = 0; jj < 128; ++jj) acc = fmaf(pp[jj], hp[jj * E_], acc);
        sh_red[tid] = acc;
        __syncthreads();
        if (jg == 0) {
            float tot = (sh_red[e] + sh_red[64 + e]) + (sh_red[128 + e] + sh_red[192 + e]);
            g_att[(size_t)(b * N_ + i) * D_ + a * E_ + e] = fmaf(tot, inv, __ldg(bbias + e));
        }
        __syncthreads();
    }
}

// ---------------------------------------------------------------------------
// GEMM-2 + fused epilogue: gate = sigmoid(feat @ H_w^T + H_b);
// out = gate * elu(g_att) + (1-gate) * feat
// ---------------------------------------------------------------------------
__device__ __forceinline__ float blend_one(float accv, float hb, float att, float f) {
    float g = 1.f / (1.f + __expf(-(accv + hb)));
    float fo = att > 0.f ? att : (__expf(att) - 1.f);
    return g * fo + (1.f - g) * f;
}

__global__ __launch_bounds__(256, 2) void gemm_gate_kernel(const float* __restrict__ Af,
                                                           const float* __restrict__ Hw,
                                                           const float* __restrict__ Hb,
                                                           float* __restrict__ out) {
    __shared__ float As[2][16][128];
    __shared__ float Bs[2][16][128];
    const int tid = threadIdx.x;
    const int m0 = blockIdx.y << 7;
    const int n0 = blockIdx.x << 7;

    const int arow = tid >> 2;
    const int acol = (tid & 3) << 2;
    const float* Ap0 = Af + (m0 + arow) * D_ + acol;
    const float* Ap1 = Ap0 + 64 * D_;

    const int hn = tid >> 1;             // 0..127
    const int hkv = (tid & 1) << 3;      // 0 or 8
    const float* Hp = Hw + (n0 + hn) * D_ + hkv;

    float4 pa0 = *(const float4*)Ap0;
    float4 pa1 = *(const float4*)Ap1;
    float4 pb0 = *(const float4*)Hp;
    float4 pb1 = *(const float4*)(Hp + 4);

    const int txb = (tid & 15) << 3;
    const int tyb = (tid >> 4) << 3;

    float acc[8][8];
#pragma unroll
    for (int i = 0; i < 8; ++i)
#pragma unroll
        for (int j = 0; j < 8; ++j) acc[i][j] = 0.f;

#define STORE_AB2(s) do {                                                     \
    As[s][acol+0][arow] = pa0.x; As[s][acol+1][arow] = pa0.y;                 \
    As[s][acol+2][arow] = pa0.z; As[s][acol+3][arow] = pa0.w;                 \
    As[s][acol+0][arow+64] = pa1.x; As[s][acol+1][arow+64] = pa1.y;           \
    As[s][acol+2][arow+64] = pa1.z; As[s][acol+3][arow+64] = pa1.w;           \
    Bs[s][hkv+0][hn] = pb0.x; Bs[s][hkv+1][hn] = pb0.y;                       \
    Bs[s][hkv+2][hn] = pb0.z; Bs[s][hkv+3][hn] = pb0.w;                       \
    Bs[s][hkv+4][hn] = pb1.x; Bs[s][hkv+5][hn] = pb1.y;                       \
    Bs[s][hkv+6][hn] = pb1.z; Bs[s][hkv+7][hn] = pb1.w; } while (0)

    STORE_AB2(0);
    __syncthreads();

    const int KT = D_ / 16;  // 48
    for (int kt = 0; kt < KT; ++kt) {
        const int s = kt & 1;
        if (kt + 1 < KT) {
            Ap0 += 16; Ap1 += 16; Hp += 16;
            pa0 = *(const float4*)Ap0;
            pa1 = *(const float4*)Ap1;
            pb0 = *(const float4*)Hp;
            pb1 = *(const float4*)(Hp + 4);
        }
#pragma unroll
        for (int k = 0; k < 16; ++k) {
            alignas(16) float ra[8], rb[8];
            *(float4*)&ra[0] = *(const float4*)&As[s][k][tyb];
            *(float4*)&ra[4] = *(const float4*)&As[s][k][tyb + 4];
            *(float4*)&rb[0] = *(const float4*)&Bs[s][k][txb];
            *(float4*)&rb[4] = *(const float4*)&Bs[s][k][txb + 4];
#pragma unroll
            for (int i = 0; i < 8; ++i)
#pragma unroll
                for (int j = 0; j < 8; ++j)
                    acc[i][j] = fmaf(ra[i], rb[j], acc[i][j]);
        }
        if (kt + 1 < KT) STORE_AB2(s ^ 1);
        __syncthreads();
    }
#undef STORE_AB2

#pragma unroll
    for (int i = 0; i < 8; ++i) {
        const int m = m0 + tyb + i;
        const float* attp = g_att + (size_t)m * D_ + n0 + txb;
        const float* fp = Af + (size_t)m * D_ + n0 + txb;
        float* op = out + (size_t)m * D_ + n0 + txb;
#pragma unroll
        for (int jv = 0; jv < 8; jv += 4) {
            float4 av = *(const float4*)(attp + jv);
            float4 fv = *(const float4*)(fp + jv);
            float4 hb = *(const float4*)(Hb + n0 + txb + jv);
            float4 ov;
            ov.x = blend_one(acc[i][jv + 0], hb.x, av.x, fv.x);
            ov.y = blend_one(acc[i][jv + 1], hb.y, av.y, fv.y);
            ov.z = blend_one(acc[i][jv + 2], hb.z, av.z, fv.z);
            ov.w = blend_one(acc[i][jv + 3], hb.w, av.w, fv.w);
            *(float4*)(op + jv) = ov;
        }
    }
}

// ---------------------------------------------------------------------------
extern "C" void kernel_launch(void* const* d_in, const int* in_sizes, int n_in,
                              void* d_out, int out_size) {
    const float* feat = (const float*)d_in[0];
    const void* adj = d_in[1];
    const float* W = (const float*)d_in[2];
    const float* bbias = (const float*)d_in[3];
    const float* wsrc = (const float*)d_in[4];
    const float* wdst = (const float*)d_in[5];
    const float* Hw = (const float*)d_in[6];
    const float* Hb = (const float*)d_in[7];
    float* out = (float*)d_out;

    detect_adj_kernel<<<1, 32>>>((const int*)adj);
    gemm_h_kernel<<<dim3(D_ / 128, M_ / 128), 256>>>(feat, W);
    srcdst_kernel<<<(B_ * A_ * N_) / 8, 256>>>(wsrc, wdst);

    const size_t att_smem = (size_t)ATT_SMEM_FLOATS * sizeof(float);
    cudaFuncSetAttribute(attn_kernel, cudaFuncAttributeMaxDynamicSharedMemorySize, (int)att_smem);
    attn_kernel<<<dim3(ISPLIT, A_, B_), 256, att_smem>>>(adj, bbias);

    gemm_gate_kernel<<<dim3(D_ / 128, M_ / 128), 256>>>(feat, Hw, Hb, out);
}

// round 3
// speedup vs baseline: 1.8091x; 1.8091x over previous
#include <cuda_runtime.h>
#include <stdint.h>

// Problem constants
#define B_ 8
#define N_ 512
#define D_ 768
#define A_ 12
#define E_ 64
#define M_ (B_ * N_)   // 4096

// Scratch (device globals: allocation-free)
__device__ float g_h[B_ * A_ * N_ * E_];     // [b][a][i][e]  12.6 MB
__device__ float g_src[B_ * A_ * N_];
__device__ float g_dst[B_ * A_ * N_];
__device__ float g_att[B_ * N_ * D_];        // [b][i][a*64+e] (attn@h + bias b)
__device__ int   g_adj_int;

// ---------------------------------------------------------------------------
// adj dtype detection
// ---------------------------------------------------------------------------
__global__ void detect_adj_kernel(const int* __restrict__ adj) {
    int ok = 1;
    for (int v = threadIdx.x; v < 1024; v += 32) {
        int w = adj[v];
        if (w != 0 && w != 1) ok = 0;
    }
#pragma unroll
    for (int o = 16; o; o >>= 1) ok &= __shfl_xor_sync(0xffffffffu, ok, o);
    if (threadIdx.x == 0) g_adj_int = ok;
}

// ---------------------------------------------------------------------------
// GEMM-1: h[b,a,i,e] = sum_d feat[b,i,d] * W[a,d,e]
// ---------------------------------------------------------------------------
__global__ __launch_bounds__(256, 2) void gemm_h_kernel(const float* __restrict__ Af,
                                                        const float* __restrict__ W) {
    __shared__ float As[2][16][128];
    __shared__ float Bs[2][16][128];
    const int tid = threadIdx.x;
    const int m0 = blockIdx.y << 7;
    const int n0 = blockIdx.x << 7;

    const int arow = tid >> 2;
    const int acol = (tid & 3) << 2;
    const float* Ap0 = Af + (m0 + arow) * D_ + acol;
    const float* Ap1 = Ap0 + 64 * D_;

    const int bk = tid >> 5;
    const int bn = (tid & 31) << 2;
    const int head = (n0 + bn) >> 6;
    const int be = (n0 + bn) & 63;
    const float* Wp0 = W + (head * D_ + bk) * E_ + be;
    const float* Wp1 = Wp0 + 8 * E_;

    float4 pa0 = *(const float4*)Ap0;
    float4 pa1 = *(const float4*)Ap1;
    float4 pb0 = *(const float4*)Wp0;
    float4 pb1 = *(const float4*)Wp1;

    const int txb = (tid & 15) << 3;
    const int tyb = (tid >> 4) << 3;

    float acc[8][8];
#pragma unroll
    for (int i = 0; i < 8; ++i)
#pragma unroll
        for (int j = 0; j < 8; ++j) acc[i][j] = 0.f;

#define STORE_AB1(s) do {                                                     \
    As[s][acol+0][arow] = pa0.x; As[s][acol+1][arow] = pa0.y;                 \
    As[s][acol+2][arow] = pa0.z; As[s][acol+3][arow] = pa0.w;                 \
    As[s][acol+0][arow+64] = pa1.x; As[s][acol+1][arow+64] = pa1.y;           \
    As[s][acol+2][arow+64] = pa1.z; As[s][acol+3][arow+64] = pa1.w;           \
    *(float4*)&Bs[s][bk][bn] = pb0;                                           \
    *(float4*)&Bs[s][bk+8][bn] = pb1; } while (0)

    STORE_AB1(0);
    __syncthreads();

    const int KT = D_ / 16;
    for (int kt = 0; kt < KT; ++kt) {
        const int s = kt & 1;
        if (kt + 1 < KT) {
            Ap0 += 16; Ap1 += 16;
            Wp0 += 16 * E_; Wp1 += 16 * E_;
            pa0 = *(const float4*)Ap0;
            pa1 = *(const float4*)Ap1;
            pb0 = *(const float4*)Wp0;
            pb1 = *(const float4*)Wp1;
        }
#pragma unroll
        for (int k = 0; k < 16; ++k) {
            alignas(16) float ra[8], rb[8];
            *(float4*)&ra[0] = *(const float4*)&As[s][k][tyb];
            *(float4*)&ra[4] = *(const float4*)&As[s][k][tyb + 4];
            *(float4*)&rb[0] = *(const float4*)&Bs[s][k][txb];
            *(float4*)&rb[4] = *(const float4*)&Bs[s][k][txb + 4];
#pragma unroll
            for (int i = 0; i < 8; ++i)
#pragma unroll
                for (int j = 0; j < 8; ++j)
                    acc[i][j] = fmaf(ra[i], rb[j], acc[i][j]);
        }
        if (kt + 1 < KT) STORE_AB1(s ^ 1);
        __syncthreads();
    }
#undef STORE_AB1

    const int bidx = m0 >> 9;
#pragma unroll
    for (int i = 0; i < 8; ++i) {
        const int m = m0 + tyb + i;
        const int irow = m & (N_ - 1);
#pragma unroll
        for (int jv = 0; jv < 8; jv += 4) {
            const int n = n0 + txb + jv;
            float4 v = make_float4(acc[i][jv], acc[i][jv + 1], acc[i][jv + 2], acc[i][jv + 3]);
            *(float4*)&g_h[(((bidx * A_) + (n >> 6)) * N_ + irow) * E_ + (n & 63)] = v;
        }
    }
}

// ---------------------------------------------------------------------------
// src/dst: warp per (b,a,i) row: tanh(h) . w_src / w_dst
// ---------------------------------------------------------------------------
__global__ void srcdst_kernel(const float* __restrict__ wsrc, const float* __restrict__ wdst) {
    const int warp = (blockIdx.x * blockDim.x + threadIdx.x) >> 5;
    const int lane = threadIdx.x & 31;
    const int a = (warp >> 9) % A_;
    const float* hr = g_h + (size_t)warp * E_;
    float t0 = tanhf(hr[lane]);
    float t1 = tanhf(hr[lane + 32]);
    float s = t0 * __ldg(wsrc + a * E_ + lane) + t1 * __ldg(wsrc + a * E_ + lane + 32);
    float d = t0 * __ldg(wdst + a * E_ + lane) + t1 * __ldg(wdst + a * E_ + lane + 32);
#pragma unroll
    for (int o = 16; o; o >>= 1) {
        s += __shfl_xor_sync(0xffffffffu, s, o);
        d += __shfl_xor_sync(0xffffffffu, d, o);
    }
    if (lane == 0) { g_src[warp] = s; g_dst[warp] = d; }
}

// ---------------------------------------------------------------------------
// Attention (restructured): block = (itile of 128, a, b).
// Phase A: h[b,a] (512x64) -> smem.
// Phase B: warp-per-row softmax stats (max, 1/sum) + packed mask bits.
// Phase C: out[128x64] = P[128x512] @ H[512x64], P recomputed on the fly
//          into a 32-wide smem tile; 8x4 register micro-GEMM per thread.
// ---------------------------------------------------------------------------
#define IT_ 128
#define KT_ 32
#define PS_STRIDE 132
// floats: Hs 32768 | Ps 4224 | src 128 | dst 512 | rmax 128 | rinv 128 | Ms 2048
#define ATT_SMEM_FLOATS (32768 + 4224 + 128 + 512 + 128 + 128 + 2048)

__global__ __launch_bounds__(256) void attn_kernel(const void* __restrict__ adjv,
                                                   const float* __restrict__ bbias) {
    extern __shared__ float sm[];
    float* Hs = sm;                            // [512][64]
    float* Ps = Hs + N_ * E_;                  // [32][132]
    float* s_src = Ps + KT_ * PS_STRIDE;       // [128]
    float* s_dst = s_src + IT_;                // [512]
    float* s_rmax = s_dst + N_;                // [128]
    float* s_rinv = s_rmax + IT_;              // [128]
    unsigned short* Ms = (unsigned short*)(s_rinv + IT_);  // [32 jwords][128 rows]

    const int tid = threadIdx.x;
    const int b = blockIdx.z, a = blockIdx.y, it = blockIdx.x;
    const int ba = b * A_ + a;
    const int i0 = it * IT_;

    // Phase A: load h tile + vectors
    {
        const float4* hsrc = (const float4*)(g_h + (size_t)ba * N_ * E_);
        float4* Hs4 = (float4*)Hs;
        for (int v = tid; v < N_ * E_ / 4; v += 256) Hs4[v] = hsrc[v];
        if (tid < IT_) s_src[tid] = g_src[ba * N_ + i0 + tid];
        s_dst[tid] = g_dst[ba * N_ + tid];
        s_dst[tid + 256] = g_dst[ba * N_ + tid + 256];
    }
    __syncthreads();

    // Phase B: stats (warp per row), pack mask bits
    const int lane = tid & 31, wid = tid >> 5;
    const int adj_int = g_adj_int;
    for (int rr = wid; rr < IT_; rr += 8) {
        const size_t rowoff = (size_t)(b * N_ + i0 + rr) * N_;
        unsigned mbits = 0;
        if (adj_int) {
            const uint4* ap = (const uint4*)((const int*)adjv + rowoff + lane * 16);
#pragma unroll
            for (int q = 0; q < 4; ++q) {
                uint4 w = ap[q];
                mbits |= (w.x ? 1u : 0u) << (q * 4 + 0);
                mbits |= (w.y ? 1u : 0u) << (q * 4 + 1);
                mbits |= (w.z ? 1u : 0u) << (q * 4 + 2);
                mbits |= (w.w ? 1u : 0u) << (q * 4 + 3);
            }
        } else {
            uint4 w = *(const uint4*)((const uint8_t*)adjv + rowoff + lane * 16);
            unsigned ws[4] = {w.x, w.y, w.z, w.w};
#pragma unroll
            for (int q = 0; q < 4; ++q)
#pragma unroll
                for (int bq = 0; bq < 4; ++bq)
                    mbits |= (((ws[q] >> (8 * bq)) & 0xffu) ? 1u : 0u) << (q * 4 + bq);
        }
        const float sbase = s_src[rr];
        alignas(16) float dv[16];
#pragma unroll
        for (int c = 0; c < 4; ++c)
            *(float4*)&dv[c * 4] = *(const float4*)&s_dst[lane * 16 + c * 4];
        float l[16];
        float mx = -1e30f;
#pragma unroll
        for (int q = 0; q < 16; ++q) {
            float v = sbase + dv[q];
            v = v >= 0.f ? v : 0.2f * v;
            l[q] = ((mbits >> q) & 1u) ? v : -999.f;
            mx = fmaxf(mx, l[q]);
        }
#pragma unroll
        for (int o = 16; o; o >>= 1) mx = fmaxf(mx, __shfl_xor_sync(0xffffffffu, mx, o));
        float ssum = 0.f;
#pragma unroll
        for (int q = 0; q < 16; ++q) ssum += __expf(l[q] - mx);
#pragma unroll
        for (int o = 16; o; o >>= 1) ssum += __shfl_xor_sync(0xffffffffu, ssum, o);
        if (lane == 0) {
            s_rmax[rr] = mx;
            s_rinv[rr] = __fdividef(1.f, ssum);
        }
        Ms[lane * IT_ + rr] = (unsigned short)mbits;  // Ms[jword][row]
    }
    __syncthreads();

    // Phase C: P @ H with on-the-fly P tiles
    const int tx = tid & 15;           // e-group: e = tx*4
    const int ty = tid >> 4;           // i-group: i = ty*8 + ii
    const int pj = tid >> 3;           // j-local in tile (0..31)
    const int il0 = (tid & 7) * 16;    // i-range for P compute

    float acc[8][4];
#pragma unroll
    for (int i = 0; i < 8; ++i)
#pragma unroll
        for (int j = 0; j < 4; ++j) acc[i][j] = 0.f;

    for (int kt = 0; kt < N_ / KT_; ++kt) {
        const int j0 = kt * KT_;
        // --- compute Ps[pj][il0..il0+15] ---
        {
            const int j = j0 + pj;
            const float dj = s_dst[j];
            const int bitj = j & 15;
            const unsigned* mp32 = (const unsigned*)(Ms + (j >> 4) * IT_ + il0);
            unsigned mw[8];
#pragma unroll
            for (int q = 0; q < 8; ++q) mw[q] = mp32[q];
#pragma unroll
            for (int c = 0; c < 4; ++c) {
                float4 sv = *(const float4*)&s_src[il0 + c * 4];
                float4 rm = *(const float4*)&s_rmax[il0 + c * 4];
                float4 ri = *(const float4*)&s_rinv[il0 + c * 4];
                float4 pv;
#pragma unroll
                for (int e = 0; e < 4; ++e) {
                    const int idx = c * 4 + e;
                    float v = (&sv.x)[e] + dj;
                    v = v >= 0.f ? v : 0.2f * v;
                    unsigned bit = (mw[idx >> 1] >> (((idx & 1) << 4) + bitj)) & 1u;
                    float lv = bit ? v : -999.f;
                    (&pv.x)[e] = __expf(lv - (&rm.x)[e]) * (&ri.x)[e];
                }
                *(float4*)&Ps[pj * PS_STRIDE + il0 + c * 4] = pv;
            }
        }
        __syncthreads();
        // --- micro-GEMM over this k-tile ---
#pragma unroll
        for (int k = 0; k < KT_; ++k) {
            float4 b4 = *(const float4*)&Hs[(j0 + k) * E_ + tx * 4];
            float4 a0 = *(const float4*)&Ps[k * PS_STRIDE + ty * 8];
            float4 a1 = *(const float4*)&Ps[k * PS_STRIDE + ty * 8 + 4];
            const float av[8] = {a0.x, a0.y, a0.z, a0.w, a1.x, a1.y, a1.z, a1.w};
#pragma unroll
            for (int i = 0; i < 8; ++i) {
                acc[i][0] = fmaf(av[i], b4.x, acc[i][0]);
                acc[i][1] = fmaf(av[i], b4.y, acc[i][1]);
                acc[i][2] = fmaf(av[i], b4.z, acc[i][2]);
                acc[i][3] = fmaf(av[i], b4.w, acc[i][3]);
            }
        }
        __syncthreads();
    }

    // Epilogue: add bias, write g_att
    float4 bias4 = *(const float4*)(bbias + tx * 4);
#pragma unroll
    for (int ii = 0; ii < 8; ++ii) {
        const int i = i0 + ty * 8 + ii;
        float4 o = make_float4(acc[ii][0] + bias4.x, acc[ii][1] + bias4.y,
                               acc[ii][2] + bias4.z, acc[ii][3] + bias4.w);
        *(float4*)&g_att[(size_t)(b * N_ + i) * D_ + a * E_ + tx * 4] = o;
    }
}

// ---------------------------------------------------------------------------
// GEMM-2 + fused epilogue
// ---------------------------------------------------------------------------
__device__ __forceinline__ float blend_one(float accv, float hb, float att, float f) {
    float g = 1.f / (1.f + __expf(-(accv + hb)));
    float fo = att > 0.f ? att : (__expf(att) - 1.f);
    return g * fo + (1.f - g) * f;
}

__global__ __launch_bounds__(256, 2) void gemm_gate_kernel(const float* __restrict__ Af,
                                                           const float* __restrict__ Hw,
                                                           const float* __restrict__ Hb,
                                                           float* __restrict__ out) {
    __shared__ float As[2][16][128];
    __shared__ float Bs[2][16][128];
    const int tid = threadIdx.x;
    const int m0 = blockIdx.y << 7;
    const int n0 = blockIdx.x << 7;

    const int arow = tid >> 2;
    const int acol = (tid & 3) << 2;
    const float* Ap0 = Af + (m0 + arow) * D_ + acol;
    const float* Ap1 = Ap0 + 64 * D_;

    const int hn = tid >> 1;
    const int hkv = (tid & 1) << 3;
    const float* Hp = Hw + (n0 + hn) * D_ + hkv;

    float4 pa0 = *(const float4*)Ap0;
    float4 pa1 = *(const float4*)Ap1;
    float4 pb0 = *(const float4*)Hp;
    float4 pb1 = *(const float4*)(Hp + 4);

    const int txb = (tid & 15) << 3;
    const int tyb = (tid >> 4) << 3;

    float acc[8][8];
#pragma unroll
    for (int i = 0; i < 8; ++i)
#pragma unroll
        for (int j = 0; j < 8; ++j) acc[i][j] = 0.f;

#define STORE_AB2(s) do {                                                     \
    As[s][acol+0][arow] = pa0.x; As[s][acol+1][arow] = pa0.y;                 \
    As[s][acol+2][arow] = pa0.z; As[s][acol+3][arow] = pa0.w;                 \
    As[s][acol+0][arow+64] = pa1.x; As[s][acol+1][arow+64] = pa1.y;           \
    As[s][acol+2][arow+64] = pa1.z; As[s][acol+3][arow+64] = pa1.w;           \
    Bs[s][hkv+0][hn] = pb0.x; Bs[s][hkv+1][hn] = pb0.y;                       \
    Bs[s][hkv+2][hn] = pb0.z; Bs[s][hkv+3][hn] = pb0.w;                       \
    Bs[s][hkv+4][hn] = pb1.x; Bs[s][hkv+5][hn] = pb1.y;                       \
    Bs[s][hkv+6][hn] = pb1.z; Bs[s][hkv+7][hn] = pb1.w; } while (0)

    STORE_AB2(0);
    __syncthreads();

    const int KT = D_ / 16;
    for (int kt = 0; kt < KT; ++kt) {
        const int s = kt & 1;
        if (kt + 1 < KT) {
            Ap0 += 16; Ap1 += 16; Hp += 16;
            pa0 = *(const float4*)Ap0;
            pa1 = *(const float4*)Ap1;
            pb0 = *(const float4*)Hp;
            pb1 = *(const float4*)(Hp + 4);
        }
#pragma unroll
        for (int k = 0; k < 16; ++k) {
            alignas(16) float ra[8], rb[8];
            *(float4*)&ra[0] = *(const float4*)&As[s][k][tyb];
            *(float4*)&ra[4] = *(const float4*)&As[s][k][tyb + 4];
            *(float4*)&rb[0] = *(const float4*)&Bs[s][k][txb];
            *(float4*)&rb[4] = *(const float4*)&Bs[s][k][txb + 4];
#pragma unroll
            for (int i = 0; i < 8; ++i)
#pragma unroll
                for (int j = 0; j < 8; ++j)
                    acc[i][j] = fmaf(ra[i], rb[j], acc[i][j]);
        }
        if (kt + 1 < KT) STORE_AB2(s ^ 1);
        __syncthreads();
    }
#undef STORE_AB2

#pragma unroll
    for (int i = 0; i < 8; ++i) {
        const int m = m0 + tyb + i;
        const float* attp = g_att + (size_t)m * D_ + n0 + txb;
        const float* fp = Af + (size_t)m * D_ + n0 + txb;
        float* op = out + (size_t)m * D_ + n0 + txb;
#pragma unroll
        for (int jv = 0; jv < 8; jv += 4) {
            float4 av = *(const float4*)(attp + jv);
            float4 fv = *(const float4*)(fp + jv);
            float4 hb = *(const float4*)(Hb + n0 + txb + jv);
            float4 ov;
            ov.x = blend_one(acc[i][jv + 0], hb.x, av.x, fv.x);
            ov.y = blend_one(acc[i][jv + 1], hb.y, av.y, fv.y);
            ov.z = blend_one(acc[i][jv + 2], hb.z, av.z, fv.z);
            ov.w = blend_one(acc[i][jv + 3], hb.w, av.w, fv.w);
            *(float4*)(op + jv) = ov;
        }
    }
}

// ---------------------------------------------------------------------------
extern "C" void kernel_launch(void* const* d_in, const int* in_sizes, int n_in,
                              void* d_out, int out_size) {
    const float* feat = (const float*)d_in[0];
    const void* adj = d_in[1];
    const float* W = (const float*)d_in[2];
    const float* bbias = (const float*)d_in[3];
    const float* wsrc = (const float*)d_in[4];
    const float* wdst = (const float*)d_in[5];
    const float* Hw = (const float*)d_in[6];
    const float* Hb = (const float*)d_in[7];
    float* out = (float*)d_out;

    detect_adj_kernel<<<1, 32>>>((const int*)adj);
    gemm_h_kernel<<<dim3(D_ / 128, M_ / 128), 256>>>(feat, W);
    srcdst_kernel<<<(B_ * A_ * N_) / 8, 256>>>(wsrc, wdst);

    const size_t att_smem = (size_t)ATT_SMEM_FLOATS * sizeof(float);
    cudaFuncSetAttribute(attn_kernel, cudaFuncAttributeMaxDynamicSharedMemorySize, (int)att_smem);
    attn_kernel<<<dim3(N_ / IT_, A_, B_), 256, att_smem>>>(adj, bbias);

    gemm_gate_kernel<<<dim3(D_ / 128, M_ / 128), 256>>>(feat, Hw, Hb, out);
}

// round 5
// speedup vs baseline: 2.3229x; 1.2840x over previous
#include <cuda_runtime.h>
#include <cuda_bf16.h>
#include <stdint.h>

// Problem constants
#define B_ 8
#define N_ 512
#define D_ 768
#define A_ 12
#define E_ 64
#define M_ (B_ * N_)   // 4096

// ---------------------------------------------------------------------------
// Scratch (device globals: allocation-free)
// ---------------------------------------------------------------------------
__device__ float g_h[B_ * A_ * N_ * E_];     // [b][a][i][e]
__device__ float g_src[B_ * A_ * N_];
__device__ float g_dst[B_ * A_ * N_];
__device__ float g_att[B_ * N_ * D_];        // [b][i][a*64+e]
__device__ int   g_adj_int;
// bf16 split operands (hi + lo)
__device__ __align__(16) __nv_bfloat16 g_fh[M_ * D_];
__device__ __align__(16) __nv_bfloat16 g_fl[M_ * D_];
__device__ __align__(16) __nv_bfloat16 g_w1h[D_ * D_];  // W^T: row n=a*64+e, col k=d
__device__ __align__(16) __nv_bfloat16 g_w1l[D_ * D_];
__device__ __align__(16) __nv_bfloat16 g_w2h[D_ * D_];  // Hw: row n, col k=d
__device__ __align__(16) __nv_bfloat16 g_w2l[D_ * D_];

// ---------------------------------------------------------------------------
// adj dtype detection
// ---------------------------------------------------------------------------
__global__ void detect_adj_kernel(const int* __restrict__ adj) {
    int ok = 1;
    for (int v = threadIdx.x; v < 1024; v += 32) {
        int w = adj[v];
        if (w != 0 && w != 1) ok = 0;
    }
#pragma unroll
    for (int o = 16; o; o >>= 1) ok &= __shfl_xor_sync(0xffffffffu, ok, o);
    if (threadIdx.x == 0) g_adj_int = ok;
}

// ---------------------------------------------------------------------------
// fp32 -> bf16 hi/lo split conversions
// ---------------------------------------------------------------------------
__device__ __forceinline__ void split2(float x, __nv_bfloat16& h, __nv_bfloat16& l) {
    h = __float2bfloat16(x);
    l = __float2bfloat16(x - __bfloat162float(h));
}

__global__ void conv_feat_kernel(const float* __restrict__ f) {
    const int g4 = (blockIdx.x * 256 + threadIdx.x) * 4;
    float4 v = *(const float4*)(f + g4);
    __nv_bfloat16 h0, h1, h2, h3, l0, l1, l2, l3;
    split2(v.x, h0, l0); split2(v.y, h1, l1); split2(v.z, h2, l2); split2(v.w, h3, l3);
    ((__nv_bfloat162*)(g_fh + g4))[0] = __nv_bfloat162(h0, h1);
    ((__nv_bfloat162*)(g_fh + g4))[1] = __nv_bfloat162(h2, h3);
    ((__nv_bfloat162*)(g_fl + g4))[0] = __nv_bfloat162(l0, l1);
    ((__nv_bfloat162*)(g_fl + g4))[1] = __nv_bfloat162(l2, l3);
}

__global__ void conv_w1_kernel(const float* __restrict__ W) {
    const int n = blockIdx.x;
    const int a = n >> 6, e = n & 63;
    for (int d = threadIdx.x; d < D_; d += 256) {
        float x = W[(a * D_ + d) * E_ + e];
        __nv_bfloat16 h, l;
        split2(x, h, l);
        g_w1h[n * D_ + d] = h;
        g_w1l[n * D_ + d] = l;
    }
}

__global__ void conv_w2_kernel(const float* __restrict__ Hw) {
    const int g4 = (blockIdx.x * 256 + threadIdx.x) * 4;
    float4 v = *(const float4*)(Hw + g4);
    __nv_bfloat16 h0, h1, h2, h3, l0, l1, l2, l3;
    split2(v.x, h0, l0); split2(v.y, h1, l1); split2(v.z, h2, l2); split2(v.w, h3, l3);
    ((__nv_bfloat162*)(g_w2h + g4))[0] = __nv_bfloat162(h0, h1);
    ((__nv_bfloat162*)(g_w2h + g4))[1] = __nv_bfloat162(h2, h3);
    ((__nv_bfloat162*)(g_w2l + g4))[0] = __nv_bfloat162(l0, l1);
    ((__nv_bfloat162*)(g_w2l + g4))[1] = __nv_bfloat162(l2, l3);
}

// ---------------------------------------------------------------------------
// HMMA bf16x3 GEMM (mma.sync m16n8k16, baseline feature — works on compute_103)
// Block tile 128x128, 8 warps (4m x 2n), warp tile 32x64.
// K chunks of 32, double-buffered SMEM, 80-byte row stride (conflict-free frags).
// ---------------------------------------------------------------------------
#define KC_ 32
#define NKC_ (D_ / KC_)          // 24
#define TROW_B 80                // bytes per smem tile row (32 bf16 + 8 pad)
#define TILE_B (128 * TROW_B)    // 10240 bytes per matrix tile
#define BUF_B (4 * TILE_B)       // 40960 bytes per buffer (Ah,Al,Bh,Bl)
#define GEMM_SMEM (2 * BUF_B)    // 81920

__device__ __forceinline__ void mma16816(float* c,
        uint32_t a0, uint32_t a1, uint32_t a2, uint32_t a3,
        uint32_t b0, uint32_t b1) {
    asm volatile(
        "mma.sync.aligned.m16n8k16.row.col.f32.bf16.bf16.f32 "
        "{%0,%1,%2,%3}, {%4,%5,%6,%7}, {%8,%9}, {%0,%1,%2,%3};"
        : "+f"(c[0]), "+f"(c[1]), "+f"(c[2]), "+f"(c[3])
        : "r"(a0), "r"(a1), "r"(a2), "r"(a3), "r"(b0), "r"(b1));
}

__device__ __forceinline__ void hmma_mainloop(
        float acc[2][8][4],
        const __nv_bfloat16* __restrict__ Ah, const __nv_bfloat16* __restrict__ Al,
        const __nv_bfloat16* __restrict__ Bh, const __nv_bfloat16* __restrict__ Bl,
        int m0, int n0, char* sm) {
    const int tid = threadIdx.x;
    const int warp = tid >> 5, lane = tid & 31;
    const int wm = warp & 3, wn = warp >> 2;
    const int g = lane >> 2, t = lane & 3;

    // gmem load mapping: thread -> row lr, 32-byte column segment
    const int lr = tid >> 1;
    const int lce = (tid & 1) * 16;                 // element offset within chunk
    const uint32_t sto = (uint32_t)lr * TROW_B + (tid & 1) * 32;

    const __nv_bfloat16* pAh = Ah + (size_t)(m0 + lr) * D_ + lce;
    const __nv_bfloat16* pAl = Al + (size_t)(m0 + lr) * D_ + lce;
    const __nv_bfloat16* pBh = Bh + (size_t)(n0 + lr) * D_ + lce;
    const __nv_bfloat16* pBl = Bl + (size_t)(n0 + lr) * D_ + lce;

    uint4 pf[4][2];
#define LDCH(kc) do {                                                        \
    pf[0][0] = *(const uint4*)(pAh + (kc) * KC_);                            \
    pf[0][1] = *(const uint4*)(pAh + (kc) * KC_ + 8);                        \
    pf[1][0] = *(const uint4*)(pAl + (kc) * KC_);                            \
    pf[1][1] = *(const uint4*)(pAl + (kc) * KC_ + 8);                        \
    pf[2][0] = *(const uint4*)(pBh + (kc) * KC_);                            \
    pf[2][1] = *(const uint4*)(pBh + (kc) * KC_ + 8);                        \
    pf[3][0] = *(const uint4*)(pBl + (kc) * KC_);                            \
    pf[3][1] = *(const uint4*)(pBl + (kc) * KC_ + 8);                        \
} while (0)
#define STCH(base) do {                                                      \
    char* _b = (base);                                                       \
    *(uint4*)(_b + sto) = pf[0][0];                                          \
    *(uint4*)(_b + sto + 16) = pf[0][1];                                     \
    *(uint4*)(_b + TILE_B + sto) = pf[1][0];                                 \
    *(uint4*)(_b + TILE_B + sto + 16) = pf[1][1];                            \
    *(uint4*)(_b + 2 * TILE_B + sto) = pf[2][0];                             \
    *(uint4*)(_b + 2 * TILE_B + sto + 16) = pf[2][1];                        \
    *(uint4*)(_b + 3 * TILE_B + sto) = pf[3][0];                             \
    *(uint4*)(_b + 3 * TILE_B + sto + 16) = pf[3][1];                        \
} while (0)

    LDCH(0);
    STCH(sm);

    int s = 0;
    for (int kc = 0; kc < NKC_; ++kc) {
        __syncthreads();
        if (kc + 1 < NKC_) LDCH(kc + 1);

        const char* sAh = sm + s * BUF_B;
        const char* sAl = sAh + TILE_B;
        const char* sBh = sAh + 2 * TILE_B;
        const char* sBl = sAh + 3 * TILE_B;

#pragma unroll
        for (int ks = 0; ks < 2; ++ks) {
            const int kb = (2 * t + ks * 16) * 2;   // byte offset of k within row
            uint32_t ah[2][4], al[2][4];
#pragma unroll
            for (int mf = 0; mf < 2; ++mf) {
                const int r0 = (wm * 32 + mf * 16 + g) * TROW_B + kb;
                ah[mf][0] = *(const uint32_t*)(sAh + r0);
                ah[mf][1] = *(const uint32_t*)(sAh + r0 + 8 * TROW_B);
                ah[mf][2] = *(const uint32_t*)(sAh + r0 + 16);
                ah[mf][3] = *(const uint32_t*)(sAh + r0 + 8 * TROW_B + 16);
                al[mf][0] = *(const uint32_t*)(sAl + r0);
                al[mf][1] = *(const uint32_t*)(sAl + r0 + 8 * TROW_B);
                al[mf][2] = *(const uint32_t*)(sAl + r0 + 16);
                al[mf][3] = *(const uint32_t*)(sAl + r0 + 8 * TROW_B + 16);
            }
#pragma unroll
            for (int nf = 0; nf < 8; ++nf) {
                const int rb = (wn * 64 + nf * 8 + g) * TROW_B + kb;
                uint32_t bh0 = *(const uint32_t*)(sBh + rb);
                uint32_t bh1 = *(const uint32_t*)(sBh + rb + 16);
                uint32_t bl0 = *(const uint32_t*)(sBl + rb);
                uint32_t bl1 = *(const uint32_t*)(sBl + rb + 16);
#pragma unroll
                for (int mf = 0; mf < 2; ++mf) {
                    mma16816(acc[mf][nf], ah[mf][0], ah[mf][1], ah[mf][2], ah[mf][3], bh0, bh1);
                    mma16816(acc[mf][nf], al[mf][0], al[mf][1], al[mf][2], al[mf][3], bh0, bh1);
                    mma16816(acc[mf][nf], ah[mf][0], ah[mf][1], ah[mf][2], ah[mf][3], bl0, bl1);
                }
            }
        }
        if (kc + 1 < NKC_) STCH(sm + (s ^ 1) * BUF_B);
        s ^= 1;
    }
#undef LDCH
#undef STCH
}

// ---------------------------------------------------------------------------
// GEMM-1 (HMMA): h = feat @ W^T -> g_h[b][a][i][e]
// ---------------------------------------------------------------------------
__global__ __launch_bounds__(256) void gemm1_tc_kernel() {
    extern __shared__ char sm[];
    const int m0 = blockIdx.y << 7;
    const int n0 = blockIdx.x << 7;
    float acc[2][8][4];
#pragma unroll
    for (int mf = 0; mf < 2; ++mf)
#pragma unroll
        for (int nf = 0; nf < 8; ++nf)
#pragma unroll
            for (int q = 0; q < 4; ++q) acc[mf][nf][q] = 0.f;

    hmma_mainloop(acc, g_fh, g_fl, g_w1h, g_w1l, m0, n0, sm);

    const int warp = threadIdx.x >> 5, lane = threadIdx.x & 31;
    const int wm = warp & 3, wn = warp >> 2;
    const int g = lane >> 2, t = lane & 3;
#pragma unroll
    for (int mf = 0; mf < 2; ++mf)
#pragma unroll
        for (int nf = 0; nf < 8; ++nf) {
            const int m = m0 + wm * 32 + mf * 16 + g;
            const int n = n0 + wn * 64 + nf * 8 + 2 * t;
            const int b = m >> 9, i = m & (N_ - 1);
            const int a = n >> 6, e = n & 63;
            float* p0 = &g_h[(((b * A_) + a) * N_ + i) * E_ + e];
            float* p1 = &g_h[(((b * A_) + a) * N_ + (i + 8)) * E_ + e];
            *(float2*)p0 = make_float2(acc[mf][nf][0], acc[mf][nf][1]);
            *(float2*)p1 = make_float2(acc[mf][nf][2], acc[mf][nf][3]);
        }
}

// ---------------------------------------------------------------------------
// GEMM-2 (HMMA) + fused epilogue:
// gate = sigmoid(feat @ Hw^T + Hb); out = gate*elu(g_att) + (1-gate)*feat
// ---------------------------------------------------------------------------
__device__ __forceinline__ float blend_one(float accv, float hb, float att, float f) {
    float gt = 1.f / (1.f + __expf(-(accv + hb)));
    float fo = att > 0.f ? att : (__expf(att) - 1.f);
    return gt * fo + (1.f - gt) * f;
}

__global__ __launch_bounds__(256) void gemm2_tc_kernel(const float* __restrict__ feat,
                                                       const float* __restrict__ Hb,
                                                       float* __restrict__ out) {
    extern __shared__ char sm[];
    const int m0 = blockIdx.y << 7;
    const int n0 = blockIdx.x << 7;
    float acc[2][8][4];
#pragma unroll
    for (int mf = 0; mf < 2; ++mf)
#pragma unroll
        for (int nf = 0; nf < 8; ++nf)
#pragma unroll
            for (int q = 0; q < 4; ++q) acc[mf][nf][q] = 0.f;

    hmma_mainloop(acc, g_fh, g_fl, g_w2h, g_w2l, m0, n0, sm);

    const int warp = threadIdx.x >> 5, lane = threadIdx.x & 31;
    const int wm = warp & 3, wn = warp >> 2;
    const int g = lane >> 2, t = lane & 3;
#pragma unroll
    for (int mf = 0; mf < 2; ++mf)
#pragma unroll
        for (int nf = 0; nf < 8; ++nf) {
            const int m = m0 + wm * 32 + mf * 16 + g;
            const int n = n0 + wn * 64 + nf * 8 + 2 * t;
            float2 hb = *(const float2*)(Hb + n);
#pragma unroll
            for (int rr = 0; rr < 2; ++rr) {
                const int mm = m + rr * 8;
                float2 av = *(const float2*)(g_att + (size_t)mm * D_ + n);
                float2 fv = *(const float2*)(feat + (size_t)mm * D_ + n);
                float2 ov;
                ov.x = blend_one(acc[mf][nf][rr * 2 + 0], hb.x, av.x, fv.x);
                ov.y = blend_one(acc[mf][nf][rr * 2 + 1], hb.y, av.y, fv.y);
                *(float2*)(out + (size_t)mm * D_ + n) = ov;
            }
        }
}

// ---------------------------------------------------------------------------
// src/dst: warp per (b,a,i) row: tanh(h) . w_src / w_dst
// ---------------------------------------------------------------------------
__global__ void srcdst_kernel(const float* __restrict__ wsrc, const float* __restrict__ wdst) {
    const int warp = (blockIdx.x * blockDim.x + threadIdx.x) >> 5;
    const int lane = threadIdx.x & 31;
    const int a = (warp >> 9) % A_;
    const float* hr = g_h + (size_t)warp * E_;
    float t0 = tanhf(hr[lane]);
    float t1 = tanhf(hr[lane + 32]);
    float s = t0 * __ldg(wsrc + a * E_ + lane) + t1 * __ldg(wsrc + a * E_ + lane + 32);
    float d = t0 * __ldg(wdst + a * E_ + lane) + t1 * __ldg(wdst + a * E_ + lane + 32);
#pragma unroll
    for (int o = 16; o; o >>= 1) {
        s += __shfl_xor_sync(0xffffffffu, s, o);
        d += __shfl_xor_sync(0xffffffffu, d, o);
    }
    if (lane == 0) { g_src[warp] = s; g_dst[warp] = d; }
}

// ---------------------------------------------------------------------------
// Attention (unchanged): block = (itile of 128, a, b)
// ---------------------------------------------------------------------------
#define IT_ 128
#define KT_ 32
#define PS_STRIDE 132
#define ATT_SMEM_FLOATS (32768 + 4224 + 128 + 512 + 128 + 128 + 2048)

__global__ __launch_bounds__(256) void attn_kernel(const void* __restrict__ adjv,
                                                   const float* __restrict__ bbias) {
    extern __shared__ float smf[];
    float* Hs = smf;
    float* Ps = Hs + N_ * E_;
    float* s_src = Ps + KT_ * PS_STRIDE;
    float* s_dst = s_src + IT_;
    float* s_rmax = s_dst + N_;
    float* s_rinv = s_rmax + IT_;
    unsigned short* Ms = (unsigned short*)(s_rinv + IT_);

    const int tid = threadIdx.x;
    const int b = blockIdx.z, a = blockIdx.y, it = blockIdx.x;
    const int ba = b * A_ + a;
    const int i0 = it * IT_;

    {
        const float4* hsrc = (const float4*)(g_h + (size_t)ba * N_ * E_);
        float4* Hs4 = (float4*)Hs;
        for (int v = tid; v < N_ * E_ / 4; v += 256) Hs4[v] = hsrc[v];
        if (tid < IT_) s_src[tid] = g_src[ba * N_ + i0 + tid];
        s_dst[tid] = g_dst[ba * N_ + tid];
        s_dst[tid + 256] = g_dst[ba * N_ + tid + 256];
    }
    __syncthreads();

    const int lane = tid & 31, wid = tid >> 5;
    const int adj_int = g_adj_int;
    for (int rr = wid; rr < IT_; rr += 8) {
        const size_t rowoff = (size_t)(b * N_ + i0 + rr) * N_;
        unsigned mbits = 0;
        if (adj_int) {
            const uint4* ap = (const uint4*)((const int*)adjv + rowoff + lane * 16);
#pragma unroll
            for (int q = 0; q < 4; ++q) {
                uint4 w = ap[q];
                mbits |= (w.x ? 1u : 0u) << (q * 4 + 0);
                mbits |= (w.y ? 1u : 0u) << (q * 4 + 1);
                mbits |= (w.z ? 1u : 0u) << (q * 4 + 2);
                mbits |= (w.w ? 1u : 0u) << (q * 4 + 3);
            }
        } else {
            uint4 w = *(const uint4*)((const uint8_t*)adjv + rowoff + lane * 16);
            unsigned ws[4] = {w.x, w.y, w.z, w.w};
#pragma unroll
            for (int q = 0; q < 4; ++q)
#pragma unroll
                for (int bq = 0; bq < 4; ++bq)
                    mbits |= (((ws[q] >> (8 * bq)) & 0xffu) ? 1u : 0u) << (q * 4 + bq);
        }
        const float sbase = s_src[rr];
        alignas(16) float dv[16];
#pragma unroll
        for (int c = 0; c < 4; ++c)
            *(float4*)&dv[c * 4] = *(const float4*)&s_dst[lane * 16 + c * 4];
        float l[16];
        float mx = -1e30f;
#pragma unroll
        for (int q = 0; q < 16; ++q) {
            float v = sbase + dv[q];
            v = v >= 0.f ? v : 0.2f * v;
            l[q] = ((mbits >> q) & 1u) ? v : -999.f;
            mx = fmaxf(mx, l[q]);
        }
#pragma unroll
        for (int o = 16; o; o >>= 1) mx = fmaxf(mx, __shfl_xor_sync(0xffffffffu, mx, o));
        float ssum = 0.f;
#pragma unroll
        for (int q = 0; q < 16; ++q) ssum += __expf(l[q] - mx);
#pragma unroll
        for (int o = 16; o; o >>= 1) ssum += __shfl_xor_sync(0xffffffffu, ssum, o);
        if (lane == 0) {
            s_rmax[rr] = mx;
            s_rinv[rr] = __fdividef(1.f, ssum);
        }
        Ms[lane * IT_ + rr] = (unsigned short)mbits;
    }
    __syncthreads();

    const int tx = tid & 15;
    const int ty = tid >> 4;
    const int pj = tid >> 3;
    const int il0 = (tid & 7) * 16;

    float acc[8][4];
#pragma unroll
    for (int i = 0; i < 8; ++i)
#pragma unroll
        for (int j = 0; j < 4; ++j) acc[i][j] = 0.f;

    for (int kt = 0; kt < N_ / KT_; ++kt) {
        const int j0 = kt * KT_;
        {
            const int j = j0 + pj;
            const float dj = s_dst[j];
            const int bitj = j & 15;
            const unsigned* mp32 = (const unsigned*)(Ms + (j >> 4) * IT_ + il0);
            unsigned mw[8];
#pragma unroll
            for (int q = 0; q < 8; ++q) mw[q] = mp32[q];
#pragma unroll
            for (int c = 0; c < 4; ++c) {
                float4 sv = *(const float4*)&s_src[il0 + c * 4];
                float4 rm = *(const float4*)&s_rmax[il0 + c * 4];
                float4 ri = *(const float4*)&s_rinv[il0 + c * 4];
                float4 pv;
#pragma unroll
                for (int e = 0; e < 4; ++e) {
                    const int idx = c * 4 + e;
                    float v = (&sv.x)[e] + dj;
                    v = v >= 0.f ? v : 0.2f * v;
                    unsigned bit = (mw[idx >> 1] >> (((idx & 1) << 4) + bitj)) & 1u;
                    float lv = bit ? v : -999.f;
                    (&pv.x)[e] = __expf(lv - (&rm.x)[e]) * (&ri.x)[e];
                }
                *(float4*)&Ps[pj * PS_STRIDE + il0 + c * 4] = pv;
            }
        }
        __syncthreads();
#pragma unroll
        for (int k = 0; k < KT_; ++k) {
            float4 b4 = *(const float4*)&Hs[(j0 + k) * E_ + tx * 4];
            float4 a0 = *(const float4*)&Ps[k * PS_STRIDE + ty * 8];
            float4 a1 = *(const float4*)&Ps[k * PS_STRIDE + ty * 8 + 4];
            const float av[8] = {a0.x, a0.y, a0.z, a0.w, a1.x, a1.y, a1.z, a1.w};
#pragma unroll
            for (int i = 0; i < 8; ++i) {
                acc[i][0] = fmaf(av[i], b4.x, acc[i][0]);
                acc[i][1] = fmaf(av[i], b4.y, acc[i][1]);
                acc[i][2] = fmaf(av[i], b4.z, acc[i][2]);
                acc[i][3] = fmaf(av[i], b4.w, acc[i][3]);
            }
        }
        __syncthreads();
    }

    float4 bias4 = *(const float4*)(bbias + tx * 4);
#pragma unroll
    for (int ii = 0; ii < 8; ++ii) {
        const int i = i0 + ty * 8 + ii;
        float4 o = make_float4(acc[ii][0] + bias4.x, acc[ii][1] + bias4.y,
                               acc[ii][2] + bias4.z, acc[ii][3] + bias4.w);
        *(float4*)&g_att[(size_t)(b * N_ + i) * D_ + a * E_ + tx * 4] = o;
    }
}

// ---------------------------------------------------------------------------
extern "C" void kernel_launch(void* const* d_in, const int* in_sizes, int n_in,
                              void* d_out, int out_size) {
    const float* feat = (const float*)d_in[0];
    const void* adj = d_in[1];
    const float* W = (const float*)d_in[2];
    const float* bbias = (const float*)d_in[3];
    const float* wsrc = (const float*)d_in[4];
    const float* wdst = (const float*)d_in[5];
    const float* Hw = (const float*)d_in[6];
    const float* Hb = (const float*)d_in[7];
    float* out = (float*)d_out;

    detect_adj_kernel<<<1, 32>>>((const int*)adj);
    conv_feat_kernel<<<M_ * D_ / 1024, 256>>>(feat);
    conv_w1_kernel<<<D_, 256>>>(W);
    conv_w2_kernel<<<D_ * D_ / 1024, 256>>>(Hw);

    cudaFuncSetAttribute(gemm1_tc_kernel, cudaFuncAttributeMaxDynamicSharedMemorySize, GEMM_SMEM);
    cudaFuncSetAttribute(gemm2_tc_kernel, cudaFuncAttributeMaxDynamicSharedMemorySize, GEMM_SMEM);

    gemm1_tc_kernel<<<dim3(D_ / 128, M_ / 128), 256, GEMM_SMEM>>>();
    srcdst_kernel<<<(B_ * A_ * N_) / 8, 256>>>(wsrc, wdst);

    const size_t att_smem = (size_t)ATT_SMEM_FLOATS * sizeof(float);
    cudaFuncSetAttribute(attn_kernel, cudaFuncAttributeMaxDynamicSharedMemorySize, (int)att_smem);
    attn_kernel<<<dim3(N_ / IT_, A_, B_), 256, att_smem>>>(adj, bbias);

    gemm2_tc_kernel<<<dim3(D_ / 128, M_ / 128), 256, GEMM_SMEM>>>(feat, Hb, out);
}

// round 6
// speedup vs baseline: 2.7792x; 1.1964x over previous
#include <cuda_runtime.h>
#include <cuda_bf16.h>
#include <stdint.h>

// Problem constants
#define B_ 8
#define N_ 512
#define D_ 768
#define A_ 12
#define E_ 64
#define M_ (B_ * N_)   // 4096

// ---------------------------------------------------------------------------
// PTX helpers (all baseline features: valid for compute_103 virtual arch)
// ---------------------------------------------------------------------------
__device__ __forceinline__ uint32_t smem_u32(const void* p) {
    uint32_t a;
    asm("{ .reg .u64 t; cvta.to.shared.u64 t, %1; cvt.u32.u64 %0, t; }" : "=r"(a) : "l"(p));
    return a;
}
__device__ __forceinline__ void ldsm_x4(uint32_t* r, uint32_t addr) {
    asm volatile("ldmatrix.sync.aligned.m8n8.x4.shared.b16 {%0,%1,%2,%3}, [%4];"
        : "=r"(r[0]), "=r"(r[1]), "=r"(r[2]), "=r"(r[3]) : "r"(addr));
}
#define CP16(dst, src) asm volatile("cp.async.cg.shared.global [%0], [%1], 16;" :: "r"(dst), "l"(src))
#define CP_COMMIT() asm volatile("cp.async.commit_group;" ::: "memory")
#define CP_WAIT1() asm volatile("cp.async.wait_group 1;" ::: "memory")
#define CP_WAIT0() asm volatile("cp.async.wait_group 0;" ::: "memory")

__device__ __forceinline__ void mma16816(float* c,
        uint32_t a0, uint32_t a1, uint32_t a2, uint32_t a3,
        uint32_t b0, uint32_t b1) {
    asm volatile(
        "mma.sync.aligned.m16n8k16.row.col.f32.bf16.bf16.f32 "
        "{%0,%1,%2,%3}, {%4,%5,%6,%7}, {%8,%9}, {%0,%1,%2,%3};"
        : "+f"(c[0]), "+f"(c[1]), "+f"(c[2]), "+f"(c[3])
        : "r"(a0), "r"(a1), "r"(a2), "r"(a3), "r"(b0), "r"(b1));
}

// ---------------------------------------------------------------------------
// Scratch (device globals: allocation-free)
// ---------------------------------------------------------------------------
__device__ float g_h[B_ * A_ * N_ * E_];     // [b][a][i][e]
__device__ float g_src[B_ * A_ * N_];
__device__ float g_dst[B_ * A_ * N_];
__device__ float g_att[B_ * N_ * D_];        // [b][i][a*64+e]
__device__ int   g_adj_int;
// bf16 split operands (hi + lo)
__device__ __align__(16) __nv_bfloat16 g_fh[M_ * D_];
__device__ __align__(16) __nv_bfloat16 g_fl[M_ * D_];
__device__ __align__(16) __nv_bfloat16 g_w1h[D_ * D_];  // W^T: row n=a*64+e, col k=d
__device__ __align__(16) __nv_bfloat16 g_w1l[D_ * D_];
__device__ __align__(16) __nv_bfloat16 g_w2h[D_ * D_];  // Hw: row n, col k=d
__device__ __align__(16) __nv_bfloat16 g_w2l[D_ * D_];

// ---------------------------------------------------------------------------
// adj dtype detection
// ---------------------------------------------------------------------------
__global__ void detect_adj_kernel(const int* __restrict__ adj) {
    int ok = 1;
    for (int v = threadIdx.x; v < 1024; v += 32) {
        int w = adj[v];
        if (w != 0 && w != 1) ok = 0;
    }
#pragma unroll
    for (int o = 16; o; o >>= 1) ok &= __shfl_xor_sync(0xffffffffu, ok, o);
    if (threadIdx.x == 0) g_adj_int = ok;
}

// ---------------------------------------------------------------------------
// fp32 -> bf16 hi/lo split conversions
// ---------------------------------------------------------------------------
__device__ __forceinline__ void split2(float x, __nv_bfloat16& h, __nv_bfloat16& l) {
    h = __float2bfloat16(x);
    l = __float2bfloat16(x - __bfloat162float(h));
}

__global__ void conv_feat_kernel(const float* __restrict__ f) {
    const int g4 = (blockIdx.x * 256 + threadIdx.x) * 4;
    float4 v = *(const float4*)(f + g4);
    __nv_bfloat16 h0, h1, h2, h3, l0, l1, l2, l3;
    split2(v.x, h0, l0); split2(v.y, h1, l1); split2(v.z, h2, l2); split2(v.w, h3, l3);
    ((__nv_bfloat162*)(g_fh + g4))[0] = __nv_bfloat162(h0, h1);
    ((__nv_bfloat162*)(g_fh + g4))[1] = __nv_bfloat162(h2, h3);
    ((__nv_bfloat162*)(g_fl + g4))[0] = __nv_bfloat162(l0, l1);
    ((__nv_bfloat162*)(g_fl + g4))[1] = __nv_bfloat162(l2, l3);
}

__global__ void conv_w1_kernel(const float* __restrict__ W) {
    const int n = blockIdx.x;
    const int a = n >> 6, e = n & 63;
    for (int d = threadIdx.x; d < D_; d += 256) {
        float x = W[(a * D_ + d) * E_ + e];
        __nv_bfloat16 h, l;
        split2(x, h, l);
        g_w1h[n * D_ + d] = h;
        g_w1l[n * D_ + d] = l;
    }
}

__global__ void conv_w2_kernel(const float* __restrict__ Hw) {
    const int g4 = (blockIdx.x * 256 + threadIdx.x) * 4;
    float4 v = *(const float4*)(Hw + g4);
    __nv_bfloat16 h0, h1, h2, h3, l0, l1, l2, l3;
    split2(v.x, h0, l0); split2(v.y, h1, l1); split2(v.z, h2, l2); split2(v.w, h3, l3);
    ((__nv_bfloat162*)(g_w2h + g4))[0] = __nv_bfloat162(h0, h1);
    ((__nv_bfloat162*)(g_w2h + g4))[1] = __nv_bfloat162(h2, h3);
    ((__nv_bfloat162*)(g_w2l + g4))[0] = __nv_bfloat162(l0, l1);
    ((__nv_bfloat162*)(g_w2l + g4))[1] = __nv_bfloat162(l2, l3);
}

// ---------------------------------------------------------------------------
// HMMA bf16x3 GEMM: 128x128 block, 8 warps (4m x 2n), warp 32x64.
// K chunks of 32; cp.async double buffer; ldmatrix fragment loads.
// ---------------------------------------------------------------------------
#define KC_ 32
#define NKC_ (D_ / KC_)          // 24
#define TROW_B 80                // bytes per smem tile row (32 bf16 + 8 pad)
#define TILE_B (128 * TROW_B)    // 10240
#define BUF_B (4 * TILE_B)       // 40960 (Ah,Al,Bh,Bl)
#define GEMM_SMEM (2 * BUF_B)    // 81920

__device__ __forceinline__ void hmma_mainloop(
        float acc[2][8][4],
        const __nv_bfloat16* __restrict__ Ah, const __nv_bfloat16* __restrict__ Al,
        const __nv_bfloat16* __restrict__ Bh, const __nv_bfloat16* __restrict__ Bl,
        int m0, int n0, char* sm) {
    const int tid = threadIdx.x;
    const int warp = tid >> 5, lane = tid & 31;
    const int wm = warp & 3, wn = warp >> 2;

    const int lr = tid >> 1;
    const int lce = (tid & 1) * 16;
    const uint32_t sto = (uint32_t)lr * TROW_B + (tid & 1) * 32;
    const uint32_t smu = smem_u32(sm);

    const __nv_bfloat16* pAh = Ah + (size_t)(m0 + lr) * D_ + lce;
    const __nv_bfloat16* pAl = Al + (size_t)(m0 + lr) * D_ + lce;
    const __nv_bfloat16* pBh = Bh + (size_t)(n0 + lr) * D_ + lce;
    const __nv_bfloat16* pBl = Bl + (size_t)(n0 + lr) * D_ + lce;

#define ISSUE(kc, buf) do {                                                  \
    uint32_t _bb = smu + (buf) * BUF_B + sto;                                \
    const int _o = (kc) * KC_;                                               \
    CP16(_bb, pAh + _o);                 CP16(_bb + 16, pAh + _o + 8);       \
    CP16(_bb + TILE_B, pAl + _o);        CP16(_bb + TILE_B + 16, pAl + _o + 8); \
    CP16(_bb + 2 * TILE_B, pBh + _o);    CP16(_bb + 2 * TILE_B + 16, pBh + _o + 8); \
    CP16(_bb + 3 * TILE_B, pBl + _o);    CP16(_bb + 3 * TILE_B + 16, pBl + _o + 8); \
    CP_COMMIT(); } while (0)

    ISSUE(0, 0);

    // ldmatrix address components
    const int arow = (lane & 7) + ((lane >> 3) & 1) * 8;
    const int acolb = (lane >> 4) * 16;
    const int brow = (lane & 7) + (lane >> 4) * 8;
    const int bcolb = ((lane >> 3) & 1) * 16;

    for (int kc = 0; kc < NKC_; ++kc) {
        if (kc + 1 < NKC_) { ISSUE(kc + 1, (kc + 1) & 1); CP_WAIT1(); }
        else               { CP_WAIT0(); }
        __syncthreads();
        const uint32_t bufb = smu + (kc & 1) * BUF_B;
        const uint32_t aA0 = bufb + (uint32_t)(wm * 32 + arow) * TROW_B + acolb;
        const uint32_t bB0 = bufb + 2 * TILE_B + (uint32_t)(wn * 64 + brow) * TROW_B + bcolb;
#pragma unroll
        for (int ks = 0; ks < 2; ++ks) {
            uint32_t ah[2][4], al[2][4], bh[4][4], bl[4][4];
#pragma unroll
            for (int mf = 0; mf < 2; ++mf) {
                ldsm_x4(ah[mf], aA0 + mf * 16 * TROW_B + ks * 32);
                ldsm_x4(al[mf], aA0 + TILE_B + mf * 16 * TROW_B + ks * 32);
            }
#pragma unroll
            for (int nfp = 0; nfp < 4; ++nfp) {
                ldsm_x4(bh[nfp], bB0 + nfp * 16 * TROW_B + ks * 32);
                ldsm_x4(bl[nfp], bB0 + TILE_B + nfp * 16 * TROW_B + ks * 32);
            }
#pragma unroll
            for (int nfp = 0; nfp < 4; ++nfp)
#pragma unroll
                for (int hf = 0; hf < 2; ++hf) {
                    const int nf = nfp * 2 + hf;
                    const uint32_t b0h = bh[nfp][hf * 2], b1h = bh[nfp][hf * 2 + 1];
                    const uint32_t b0l = bl[nfp][hf * 2], b1l = bl[nfp][hf * 2 + 1];
#pragma unroll
                    for (int mf = 0; mf < 2; ++mf) {
                        mma16816(acc[mf][nf], ah[mf][0], ah[mf][1], ah[mf][2], ah[mf][3], b0h, b1h);
                        mma16816(acc[mf][nf], al[mf][0], al[mf][1], al[mf][2], al[mf][3], b0h, b1h);
                        mma16816(acc[mf][nf], ah[mf][0], ah[mf][1], ah[mf][2], ah[mf][3], b0l, b1l);
                    }
                }
        }
        __syncthreads();
    }
#undef ISSUE
}

// ---------------------------------------------------------------------------
// GEMM-1 (HMMA): h = feat @ W^T -> g_h[b][a][i][e]
// ---------------------------------------------------------------------------
__global__ __launch_bounds__(256) void gemm1_tc_kernel() {
    extern __shared__ char sm[];
    const int m0 = blockIdx.y << 7;
    const int n0 = blockIdx.x << 7;
    float acc[2][8][4];
#pragma unroll
    for (int mf = 0; mf < 2; ++mf)
#pragma unroll
        for (int nf = 0; nf < 8; ++nf)
#pragma unroll
            for (int q = 0; q < 4; ++q) acc[mf][nf][q] = 0.f;

    hmma_mainloop(acc, g_fh, g_fl, g_w1h, g_w1l, m0, n0, sm);

    const int warp = threadIdx.x >> 5, lane = threadIdx.x & 31;
    const int wm = warp & 3, wn = warp >> 2;
    const int g = lane >> 2, t = lane & 3;
#pragma unroll
    for (int mf = 0; mf < 2; ++mf)
#pragma unroll
        for (int nf = 0; nf < 8; ++nf) {
            const int m = m0 + wm * 32 + mf * 16 + g;
            const int n = n0 + wn * 64 + nf * 8 + 2 * t;
            const int b = m >> 9, i = m & (N_ - 1);
            const int a = n >> 6, e = n & 63;
            float* p0 = &g_h[(((b * A_) + a) * N_ + i) * E_ + e];
            float* p1 = &g_h[(((b * A_) + a) * N_ + (i + 8)) * E_ + e];
            *(float2*)p0 = make_float2(acc[mf][nf][0], acc[mf][nf][1]);
            *(float2*)p1 = make_float2(acc[mf][nf][2], acc[mf][nf][3]);
        }
}

// ---------------------------------------------------------------------------
// GEMM-2 (HMMA) + fused epilogue:
// gate = sigmoid(feat @ Hw^T + Hb); out = gate*elu(g_att) + (1-gate)*feat
// ---------------------------------------------------------------------------
__device__ __forceinline__ float blend_one(float accv, float hb, float att, float f) {
    float gt = 1.f / (1.f + __expf(-(accv + hb)));
    float fo = att > 0.f ? att : (__expf(att) - 1.f);
    return gt * fo + (1.f - gt) * f;
}

__global__ __launch_bounds__(256) void gemm2_tc_kernel(const float* __restrict__ feat,
                                                       const float* __restrict__ Hb,
                                                       float* __restrict__ out) {
    extern __shared__ char sm[];
    const int m0 = blockIdx.y << 7;
    const int n0 = blockIdx.x << 7;
    float acc[2][8][4];
#pragma unroll
    for (int mf = 0; mf < 2; ++mf)
#pragma unroll
        for (int nf = 0; nf < 8; ++nf)
#pragma unroll
            for (int q = 0; q < 4; ++q) acc[mf][nf][q] = 0.f;

    hmma_mainloop(acc, g_fh, g_fl, g_w2h, g_w2l, m0, n0, sm);

    const int warp = threadIdx.x >> 5, lane = threadIdx.x & 31;
    const int wm = warp & 3, wn = warp >> 2;
    const int g = lane >> 2, t = lane & 3;
#pragma unroll
    for (int mf = 0; mf < 2; ++mf)
#pragma unroll
        for (int nf = 0; nf < 8; ++nf) {
            const int m = m0 + wm * 32 + mf * 16 + g;
            const int n = n0 + wn * 64 + nf * 8 + 2 * t;
            float2 hb = *(const float2*)(Hb + n);
#pragma unroll
            for (int rr = 0; rr < 2; ++rr) {
                const int mm = m + rr * 8;
                float2 av = *(const float2*)(g_att + (size_t)mm * D_ + n);
                float2 fv = *(const float2*)(feat + (size_t)mm * D_ + n);
                float2 ov;
                ov.x = blend_one(acc[mf][nf][rr * 2 + 0], hb.x, av.x, fv.x);
                ov.y = blend_one(acc[mf][nf][rr * 2 + 1], hb.y, av.y, fv.y);
                *(float2*)(out + (size_t)mm * D_ + n) = ov;
            }
        }
}

// ---------------------------------------------------------------------------
// src/dst: warp per (b,a,i) row: tanh(h) . w_src / w_dst
// ---------------------------------------------------------------------------
__global__ void srcdst_kernel(const float* __restrict__ wsrc, const float* __restrict__ wdst) {
    const int warp = (blockIdx.x * blockDim.x + threadIdx.x) >> 5;
    const int lane = threadIdx.x & 31;
    const int a = (warp >> 9) % A_;
    const float* hr = g_h + (size_t)warp * E_;
    float t0 = tanhf(hr[lane]);
    float t1 = tanhf(hr[lane + 32]);
    float s = t0 * __ldg(wsrc + a * E_ + lane) + t1 * __ldg(wsrc + a * E_ + lane + 32);
    float d = t0 * __ldg(wdst + a * E_ + lane) + t1 * __ldg(wdst + a * E_ + lane + 32);
#pragma unroll
    for (int o = 16; o; o >>= 1) {
        s += __shfl_xor_sync(0xffffffffu, s, o);
        d += __shfl_xor_sync(0xffffffffu, d, o);
    }
    if (lane == 0) { g_src[warp] = s; g_dst[warp] = d; }
}

// ---------------------------------------------------------------------------
// Attention (HMMA): block = (itile of 128, a, b), 8 warps.
// Phase A: h[b,a] -> transposed bf16 hi/lo HT[e][j] in smem.
// Phase B: warp-per-row softmax stats (max, 1/sum) + packed mask bits.
// Phase C: 8 chunks of 64 j: recompute P -> bf16 hi/lo tile, then
//          HMMA  Ph@Hh + Pl@Hh + Ph@Hl  (fp32 accum).
// ---------------------------------------------------------------------------
#define HT_ROWB 1040             // 512 bf16 + 8 pad
#define P_ROWB 144               // 64 bf16 + 8 pad
#define OFF_HTH 0
#define OFF_HTL 66560
#define OFF_PBH 133120
#define OFF_PBL 151552
#define OFF_SRC 169984
#define OFF_DST 170496
#define OFF_RMX 172544
#define OFF_RIV 173056
#define OFF_MS  173568
#define ATT_SMEM_B (OFF_MS + 8192)   // 181760

__global__ __launch_bounds__(256) void attn_kernel(const void* __restrict__ adjv,
                                                   const float* __restrict__ bbias) {
    extern __shared__ char sm[];
    const uint32_t smu = smem_u32(sm);
    char* HTh = sm + OFF_HTH;
    char* HTl = sm + OFF_HTL;
    char* Pbh = sm + OFF_PBH;
    char* Pbl = sm + OFF_PBL;
    float* s_src = (float*)(sm + OFF_SRC);
    float* s_dst = (float*)(sm + OFF_DST);
    float* s_rmax = (float*)(sm + OFF_RMX);
    float* s_rinv = (float*)(sm + OFF_RIV);
    unsigned short* Ms = (unsigned short*)(sm + OFF_MS);   // [32 jwords][128 rows]

    const int tid = threadIdx.x;
    const int lane = tid & 31, warp = tid >> 5;
    const int b = blockIdx.z, a = blockIdx.y, it = blockIdx.x;
    const int ba = b * A_ + a;
    const int i0 = it * 128;

    // ---- Phase A: transpose + split h into HT; load vectors ----
    {
        const float4* hsrc = (const float4*)(g_h + (size_t)ba * N_ * E_);
        for (int v = tid; v < N_ * E_ / 4; v += 256) {
            float4 x = hsrc[v];
            const int j = v >> 4;
            const int e0 = (v & 15) << 2;
#pragma unroll
            for (int q = 0; q < 4; ++q) {
                __nv_bfloat16 hh, ll;
                split2((&x.x)[q], hh, ll);
                *(__nv_bfloat16*)(HTh + (e0 + q) * HT_ROWB + j * 2) = hh;
                *(__nv_bfloat16*)(HTl + (e0 + q) * HT_ROWB + j * 2) = ll;
            }
        }
        if (tid < 128) s_src[tid] = g_src[ba * N_ + i0 + tid];
        s_dst[tid] = g_dst[ba * N_ + tid];
        s_dst[tid + 256] = g_dst[ba * N_ + tid + 256];
    }
    __syncthreads();

    // ---- Phase B: stats (warp per row), packed mask bits ----
    const int adj_int = g_adj_int;
    for (int rr = warp; rr < 128; rr += 8) {
        const size_t rowoff = (size_t)(b * N_ + i0 + rr) * N_;
        unsigned mbits = 0;
        if (adj_int) {
            const uint4* ap = (const uint4*)((const int*)adjv + rowoff + lane * 16);
#pragma unroll
            for (int q = 0; q < 4; ++q) {
                uint4 w = ap[q];
                mbits |= (w.x ? 1u : 0u) << (q * 4 + 0);
                mbits |= (w.y ? 1u : 0u) << (q * 4 + 1);
                mbits |= (w.z ? 1u : 0u) << (q * 4 + 2);
                mbits |= (w.w ? 1u : 0u) << (q * 4 + 3);
            }
        } else {
            uint4 w = *(const uint4*)((const uint8_t*)adjv + rowoff + lane * 16);
            unsigned ws[4] = {w.x, w.y, w.z, w.w};
#pragma unroll
            for (int q = 0; q < 4; ++q)
#pragma unroll
                for (int bq = 0; bq < 4; ++bq)
                    mbits |= (((ws[q] >> (8 * bq)) & 0xffu) ? 1u : 0u) << (q * 4 + bq);
        }
        const float sbase = s_src[rr];
        alignas(16) float dv[16];
#pragma unroll
        for (int c = 0; c < 4; ++c)
            *(float4*)&dv[c * 4] = *(const float4*)&s_dst[lane * 16 + c * 4];
        float l[16];
        float mx = -1e30f;
#pragma unroll
        for (int q = 0; q < 16; ++q) {
            float v = sbase + dv[q];
            v = v >= 0.f ? v : 0.2f * v;
            l[q] = ((mbits >> q) & 1u) ? v : -999.f;
            mx = fmaxf(mx, l[q]);
        }
#pragma unroll
        for (int o = 16; o; o >>= 1) mx = fmaxf(mx, __shfl_xor_sync(0xffffffffu, mx, o));
        float ssum = 0.f;
#pragma unroll
        for (int q = 0; q < 16; ++q) ssum += __expf(l[q] - mx);
#pragma unroll
        for (int o = 16; o; o >>= 1) ssum += __shfl_xor_sync(0xffffffffu, ssum, o);
        if (lane == 0) {
            s_rmax[rr] = mx;
            s_rinv[rr] = __fdividef(1.f, ssum);
        }
        Ms[lane * 128 + rr] = (unsigned short)mbits;   // Ms[jword][row]
    }
    __syncthreads();

    // ---- Phase C: P tiles + HMMA ----
    const int wm = warp & 3, wn = warp >> 2;
    const int r = tid >> 1, jseg = (tid & 1) * 32;
    const float srcv = s_src[r], rmaxv = s_rmax[r], rinvv = s_rinv[r];

    const int arow = (lane & 7) + ((lane >> 3) & 1) * 8;
    const int acolb = (lane >> 4) * 16;
    const int brow = (lane & 7) + (lane >> 4) * 8;
    const int bcolb = ((lane >> 3) & 1) * 16;
    const uint32_t aP0 = smu + OFF_PBH + (uint32_t)(wm * 32 + arow) * P_ROWB + acolb;
    const uint32_t bH0 = smu + OFF_HTH + (uint32_t)(wn * 32 + brow) * HT_ROWB + bcolb;

    float acc[2][4][4];
#pragma unroll
    for (int mf = 0; mf < 2; ++mf)
#pragma unroll
        for (int nf = 0; nf < 4; ++nf)
#pragma unroll
            for (int q = 0; q < 4; ++q) acc[mf][nf][q] = 0.f;

    for (int jc = 0; jc < 8; ++jc) {
        const int j0 = jc * 64;
        // compute P chunk: this thread covers row r, j in [j0+jseg, j0+jseg+32)
        {
            const int jb = j0 + jseg;
            uint32_t mw0 = Ms[(jb >> 4) * 128 + r];
            uint32_t mw1 = Ms[((jb >> 4) + 1) * 128 + r];
            uint32_t mbits = mw0 | (mw1 << 16);
#pragma unroll
            for (int q = 0; q < 32; q += 2) {
                float d0 = s_dst[jb + q];
                float d1 = s_dst[jb + q + 1];
                float l0 = srcv + d0; l0 = l0 >= 0.f ? l0 : 0.2f * l0;
                float l1 = srcv + d1; l1 = l1 >= 0.f ? l1 : 0.2f * l1;
                if (!((mbits >> q) & 1u)) l0 = -999.f;
                if (!((mbits >> (q + 1)) & 1u)) l1 = -999.f;
                float p0 = __expf(l0 - rmaxv) * rinvv;
                float p1 = __expf(l1 - rmaxv) * rinvv;
                __nv_bfloat16 h0, lo0, h1, lo1;
                split2(p0, h0, lo0);
                split2(p1, h1, lo1);
                *(__nv_bfloat162*)(Pbh + r * P_ROWB + (jseg + q) * 2) = __nv_bfloat162(h0, h1);
                *(__nv_bfloat162*)(Pbl + r * P_ROWB + (jseg + q) * 2) = __nv_bfloat162(lo0, lo1);
            }
        }
        __syncthreads();
        // HMMA over this chunk (K=64 -> 4 k16 steps)
#pragma unroll
        for (int ks = 0; ks < 4; ++ks) {
            uint32_t ah[2][4], al[2][4], bh[2][4], bl[2][4];
#pragma unroll
            for (int mf = 0; mf < 2; ++mf) {
                ldsm_x4(ah[mf], aP0 + mf * 16 * P_ROWB + ks * 32);
                ldsm_x4(al[mf], aP0 + (OFF_PBL - OFF_PBH) + mf * 16 * P_ROWB + ks * 32);
            }
#pragma unroll
            for (int nfp = 0; nfp < 2; ++nfp) {
                ldsm_x4(bh[nfp], bH0 + nfp * 16 * HT_ROWB + j0 * 2 + ks * 32);
                ldsm_x4(bl[nfp], bH0 + (OFF_HTL - OFF_HTH) + nfp * 16 * HT_ROWB + j0 * 2 + ks * 32);
            }
#pragma unroll
            for (int nfp = 0; nfp < 2; ++nfp)
#pragma unroll
                for (int hf = 0; hf < 2; ++hf) {
                    const int nf = nfp * 2 + hf;
                    const uint32_t b0h = bh[nfp][hf * 2], b1h = bh[nfp][hf * 2 + 1];
                    const uint32_t b0l = bl[nfp][hf * 2], b1l = bl[nfp][hf * 2 + 1];
#pragma unroll
                    for (int mf = 0; mf < 2; ++mf) {
                        mma16816(acc[mf][nf], ah[mf][0], ah[mf][1], ah[mf][2], ah[mf][3], b0h, b1h);
                        mma16816(acc[mf][nf], al[mf][0], al[mf][1], al[mf][2], al[mf][3], b0h, b1h);
                        mma16816(acc[mf][nf], ah[mf][0], ah[mf][1], ah[mf][2], ah[mf][3], b0l, b1l);
                    }
                }
        }
        __syncthreads();
    }

    // ---- epilogue: bias + store to g_att ----
    const int g = lane >> 2, t = lane & 3;
#pragma unroll
    for (int mf = 0; mf < 2; ++mf)
#pragma unroll
        for (int nf = 0; nf < 4; ++nf) {
            const int row = i0 + wm * 32 + mf * 16 + g;
            const int col = wn * 32 + nf * 8 + 2 * t;
            float2 bias = *(const float2*)(bbias + col);
            float2 v0 = make_float2(acc[mf][nf][0] + bias.x, acc[mf][nf][1] + bias.y);
            float2 v1 = make_float2(acc[mf][nf][2] + bias.x, acc[mf][nf][3] + bias.y);
            *(float2*)&g_att[(size_t)(b * N_ + row) * D_ + a * E_ + col] = v0;
            *(float2*)&g_att[(size_t)(b * N_ + row + 8) * D_ + a * E_ + col] = v1;
        }
}

// ---------------------------------------------------------------------------
extern "C" void kernel_launch(void* const* d_in, const int* in_sizes, int n_in,
                              void* d_out, int out_size) {
    const float* feat = (const float*)d_in[0];
    const void* adj = d_in[1];
    const float* W = (const float*)d_in[2];
    const float* bbias = (const float*)d_in[3];
    const float* wsrc = (const float*)d_in[4];
    const float* wdst = (const float*)d_in[5];
    const float* Hw = (const float*)d_in[6];
    const float* Hb = (const float*)d_in[7];
    float* out = (float*)d_out;

    detect_adj_kernel<<<1, 32>>>((const int*)adj);
    conv_feat_kernel<<<M_ * D_ / 1024, 256>>>(feat);
    conv_w1_kernel<<<D_, 256>>>(W);
    conv_w2_kernel<<<D_ * D_ / 1024, 256>>>(Hw);

    cudaFuncSetAttribute(gemm1_tc_kernel, cudaFuncAttributeMaxDynamicSharedMemorySize, GEMM_SMEM);
    cudaFuncSetAttribute(gemm2_tc_kernel, cudaFuncAttributeMaxDynamicSharedMemorySize, GEMM_SMEM);
    cudaFuncSetAttribute(attn_kernel, cudaFuncAttributeMaxDynamicSharedMemorySize, ATT_SMEM_B);

    gemm1_tc_kernel<<<dim3(D_ / 128, M_ / 128), 256, GEMM_SMEM>>>();
    srcdst_kernel<<<(B_ * A_ * N_) / 8, 256>>>(wsrc, wdst);

    attn_kernel<<<dim3(N_ / 128, A_, B_), 256, ATT_SMEM_B>>>(adj, bbias);

    gemm2_tc_kernel<<<dim3(D_ / 128, M_ / 128), 256, GEMM_SMEM>>>(feat, Hb, out);
}

// round 7
// speedup vs baseline: 2.7811x; 1.0007x over previous
#include <cuda_runtime.h>
#include <cuda_bf16.h>
#include <stdint.h>

// Problem constants
#define B_ 8
#define N_ 512
#define D_ 768
#define A_ 12
#define E_ 64
#define M_ (B_ * N_)   // 4096

// ---------------------------------------------------------------------------
// PTX helpers (all baseline features: valid for compute_103 virtual arch)
// ---------------------------------------------------------------------------
__device__ __forceinline__ uint32_t smem_u32(const void* p) {
    uint32_t a;
    asm("{ .reg .u64 t; cvta.to.shared.u64 t, %1; cvt.u32.u64 %0, t; }" : "=r"(a) : "l"(p));
    return a;
}
__device__ __forceinline__ void ldsm_x4(uint32_t* r, uint32_t addr) {
    asm volatile("ldmatrix.sync.aligned.m8n8.x4.shared.b16 {%0,%1,%2,%3}, [%4];"
        : "=r"(r[0]), "=r"(r[1]), "=r"(r[2]), "=r"(r[3]) : "r"(addr));
}
#define CP16(dst, src) asm volatile("cp.async.cg.shared.global [%0], [%1], 16;" :: "r"(dst), "l"(src))
#define CP_COMMIT() asm volatile("cp.async.commit_group;" ::: "memory")
#define CP_WAIT1() asm volatile("cp.async.wait_group 1;" ::: "memory")
#define CP_WAIT0() asm volatile("cp.async.wait_group 0;" ::: "memory")

__device__ __forceinline__ void mma16816(float* c,
        uint32_t a0, uint32_t a1, uint32_t a2, uint32_t a3,
        uint32_t b0, uint32_t b1) {
    asm volatile(
        "mma.sync.aligned.m16n8k16.row.col.f32.bf16.bf16.f32 "
        "{%0,%1,%2,%3}, {%4,%5,%6,%7}, {%8,%9}, {%0,%1,%2,%3};"
        : "+f"(c[0]), "+f"(c[1]), "+f"(c[2]), "+f"(c[3])
        : "r"(a0), "r"(a1), "r"(a2), "r"(a3), "r"(b0), "r"(b1));
}

// ---------------------------------------------------------------------------
// Scratch (device globals: allocation-free)
// ---------------------------------------------------------------------------
__device__ float g_h[B_ * A_ * N_ * E_];     // [b][a][i][e]
__device__ float g_src[B_ * A_ * N_];
__device__ float g_dst[B_ * A_ * N_];
__device__ float g_att[B_ * N_ * D_];        // [b][i][a*64+e]
__device__ int   g_adj_int;
// bf16 split operands (hi + lo)
__device__ __align__(16) __nv_bfloat16 g_fh[M_ * D_];
__device__ __align__(16) __nv_bfloat16 g_fl[M_ * D_];
__device__ __align__(16) __nv_bfloat16 g_w1h[D_ * D_];  // W^T: row n=a*64+e, col k=d
__device__ __align__(16) __nv_bfloat16 g_w1l[D_ * D_];
__device__ __align__(16) __nv_bfloat16 g_w2h[D_ * D_];  // Hw: row n, col k=d
__device__ __align__(16) __nv_bfloat16 g_w2l[D_ * D_];

// ---------------------------------------------------------------------------
// adj dtype detection
// ---------------------------------------------------------------------------
__global__ void detect_adj_kernel(const int* __restrict__ adj) {
    int ok = 1;
    for (int v = threadIdx.x; v < 1024; v += 32) {
        int w = adj[v];
        if (w != 0 && w != 1) ok = 0;
    }
#pragma unroll
    for (int o = 16; o; o >>= 1) ok &= __shfl_xor_sync(0xffffffffu, ok, o);
    if (threadIdx.x == 0) g_adj_int = ok;
}

// ---------------------------------------------------------------------------
// fp32 -> bf16 hi/lo split conversions
// ---------------------------------------------------------------------------
__device__ __forceinline__ void split2(float x, __nv_bfloat16& h, __nv_bfloat16& l) {
    h = __float2bfloat16(x);
    l = __float2bfloat16(x - __bfloat162float(h));
}

__global__ void conv_feat_kernel(const float* __restrict__ f) {
    const int g4 = (blockIdx.x * 256 + threadIdx.x) * 4;
    float4 v = *(const float4*)(f + g4);
    __nv_bfloat16 h0, h1, h2, h3, l0, l1, l2, l3;
    split2(v.x, h0, l0); split2(v.y, h1, l1); split2(v.z, h2, l2); split2(v.w, h3, l3);
    ((__nv_bfloat162*)(g_fh + g4))[0] = __nv_bfloat162(h0, h1);
    ((__nv_bfloat162*)(g_fh + g4))[1] = __nv_bfloat162(h2, h3);
    ((__nv_bfloat162*)(g_fl + g4))[0] = __nv_bfloat162(l0, l1);
    ((__nv_bfloat162*)(g_fl + g4))[1] = __nv_bfloat162(l2, l3);
}

__global__ void conv_w1_kernel(const float* __restrict__ W) {
    const int n = blockIdx.x;
    const int a = n >> 6, e = n & 63;
    for (int d = threadIdx.x; d < D_; d += 256) {
        float x = W[(a * D_ + d) * E_ + e];
        __nv_bfloat16 h, l;
        split2(x, h, l);
        g_w1h[n * D_ + d] = h;
        g_w1l[n * D_ + d] = l;
    }
}

__global__ void conv_w2_kernel(const float* __restrict__ Hw) {
    const int g4 = (blockIdx.x * 256 + threadIdx.x) * 4;
    float4 v = *(const float4*)(Hw + g4);
    __nv_bfloat16 h0, h1, h2, h3, l0, l1, l2, l3;
    split2(v.x, h0, l0); split2(v.y, h1, l1); split2(v.z, h2, l2); split2(v.w, h3, l3);
    ((__nv_bfloat162*)(g_w2h + g4))[0] = __nv_bfloat162(h0, h1);
    ((__nv_bfloat162*)(g_w2h + g4))[1] = __nv_bfloat162(h2, h3);
    ((__nv_bfloat162*)(g_w2l + g4))[0] = __nv_bfloat162(l0, l1);
    ((__nv_bfloat162*)(g_w2l + g4))[1] = __nv_bfloat162(l2, l3);
}

// ---------------------------------------------------------------------------
// HMMA bf16x3 GEMM: 128x128 block, 8 warps (4m x 2n), warp 32x64.
// K chunks of 32; cp.async double buffer; ldmatrix fragment loads.
// ---------------------------------------------------------------------------
#define KC_ 32
#define NKC_ (D_ / KC_)          // 24
#define TROW_B 80                // bytes per smem tile row (32 bf16 + 8 pad)
#define TILE_B (128 * TROW_B)    // 10240
#define BUF_B (4 * TILE_B)       // 40960 (Ah,Al,Bh,Bl)
#define GEMM_SMEM (2 * BUF_B)    // 81920

__device__ __forceinline__ void hmma_mainloop(
        float acc[2][8][4],
        const __nv_bfloat16* __restrict__ Ah, const __nv_bfloat16* __restrict__ Al,
        const __nv_bfloat16* __restrict__ Bh, const __nv_bfloat16* __restrict__ Bl,
        int m0, int n0, char* sm) {
    const int tid = threadIdx.x;
    const int warp = tid >> 5, lane = tid & 31;
    const int wm = warp & 3, wn = warp >> 2;

    const int lr = tid >> 1;
    const int lce = (tid & 1) * 16;
    const uint32_t sto = (uint32_t)lr * TROW_B + (tid & 1) * 32;
    const uint32_t smu = smem_u32(sm);

    const __nv_bfloat16* pAh = Ah + (size_t)(m0 + lr) * D_ + lce;
    const __nv_bfloat16* pAl = Al + (size_t)(m0 + lr) * D_ + lce;
    const __nv_bfloat16* pBh = Bh + (size_t)(n0 + lr) * D_ + lce;
    const __nv_bfloat16* pBl = Bl + (size_t)(n0 + lr) * D_ + lce;

#define ISSUE(kc, buf) do {                                                  \
    uint32_t _bb = smu + (buf) * BUF_B + sto;                                \
    const int _o = (kc) * KC_;                                               \
    CP16(_bb, pAh + _o);                 CP16(_bb + 16, pAh + _o + 8);       \
    CP16(_bb + TILE_B, pAl + _o);        CP16(_bb + TILE_B + 16, pAl + _o + 8); \
    CP16(_bb + 2 * TILE_B, pBh + _o);    CP16(_bb + 2 * TILE_B + 16, pBh + _o + 8); \
    CP16(_bb + 3 * TILE_B, pBl + _o);    CP16(_bb + 3 * TILE_B + 16, pBl + _o + 8); \
    CP_COMMIT(); } while (0)

    ISSUE(0, 0);

    // ldmatrix address components
    const int arow = (lane & 7) + ((lane >> 3) & 1) * 8;
    const int acolb = (lane >> 4) * 16;
    const int brow = (lane & 7) + (lane >> 4) * 8;
    const int bcolb = ((lane >> 3) & 1) * 16;

    for (int kc = 0; kc < NKC_; ++kc) {
        if (kc + 1 < NKC_) { ISSUE(kc + 1, (kc + 1) & 1); CP_WAIT1(); }
        else               { CP_WAIT0(); }
        __syncthreads();
        const uint32_t bufb = smu + (kc & 1) * BUF_B;
        const uint32_t aA0 = bufb + (uint32_t)(wm * 32 + arow) * TROW_B + acolb;
        const uint32_t bB0 = bufb + 2 * TILE_B + (uint32_t)(wn * 64 + brow) * TROW_B + bcolb;
#pragma unroll
        for (int ks = 0; ks < 2; ++ks) {
            uint32_t ah[2][4], al[2][4], bh[4][4], bl[4][4];
#pragma unroll
            for (int mf = 0; mf < 2; ++mf) {
                ldsm_x4(ah[mf], aA0 + mf * 16 * TROW_B + ks * 32);
                ldsm_x4(al[mf], aA0 + TILE_B + mf * 16 * TROW_B + ks * 32);
            }
#pragma unroll
            for (int nfp = 0; nfp < 4; ++nfp) {
                ldsm_x4(bh[nfp], bB0 + nfp * 16 * TROW_B + ks * 32);
                ldsm_x4(bl[nfp], bB0 + TILE_B + nfp * 16 * TROW_B + ks * 32);
            }
#pragma unroll
            for (int nfp = 0; nfp < 4; ++nfp)
#pragma unroll
                for (int hf = 0; hf < 2; ++hf) {
                    const int nf = nfp * 2 + hf;
                    const uint32_t b0h = bh[nfp][hf * 2], b1h = bh[nfp][hf * 2 + 1];
                    const uint32_t b0l = bl[nfp][hf * 2], b1l = bl[nfp][hf * 2 + 1];
#pragma unroll
                    for (int mf = 0; mf < 2; ++mf) {
                        mma16816(acc[mf][nf], ah[mf][0], ah[mf][1], ah[mf][2], ah[mf][3], b0h, b1h);
                        mma16816(acc[mf][nf], al[mf][0], al[mf][1], al[mf][2], al[mf][3], b0h, b1h);
                        mma16816(acc[mf][nf], ah[mf][0], ah[mf][1], ah[mf][2], ah[mf][3], b0l, b1l);
                    }
                }
        }
        __syncthreads();
    }
#undef ISSUE
}

// ---------------------------------------------------------------------------
// GEMM-1 (HMMA): h = feat @ W^T -> g_h[b][a][i][e]
// ---------------------------------------------------------------------------
__global__ __launch_bounds__(256) void gemm1_tc_kernel() {
    extern __shared__ char sm[];
    const int m0 = blockIdx.y << 7;
    const int n0 = blockIdx.x << 7;
    float acc[2][8][4];
#pragma unroll
    for (int mf = 0; mf < 2; ++mf)
#pragma unroll
        for (int nf = 0; nf < 8; ++nf)
#pragma unroll
            for (int q = 0; q < 4; ++q) acc[mf][nf][q] = 0.f;

    hmma_mainloop(acc, g_fh, g_fl, g_w1h, g_w1l, m0, n0, sm);

    const int warp = threadIdx.x >> 5, lane = threadIdx.x & 31;
    const int wm = warp & 3, wn = warp >> 2;
    const int g = lane >> 2, t = lane & 3;
#pragma unroll
    for (int mf = 0; mf < 2; ++mf)
#pragma unroll
        for (int nf = 0; nf < 8; ++nf) {
            const int m = m0 + wm * 32 + mf * 16 + g;
            const int n = n0 + wn * 64 + nf * 8 + 2 * t;
            const int b = m >> 9, i = m & (N_ - 1);
            const int a = n >> 6, e = n & 63;
            float* p0 = &g_h[(((b * A_) + a) * N_ + i) * E_ + e];
            float* p1 = &g_h[(((b * A_) + a) * N_ + (i + 8)) * E_ + e];
            *(float2*)p0 = make_float2(acc[mf][nf][0], acc[mf][nf][1]);
            *(float2*)p1 = make_float2(acc[mf][nf][2], acc[mf][nf][3]);
        }
}

// ---------------------------------------------------------------------------
// GEMM-2 (HMMA) + fused epilogue:
// gate = sigmoid(feat @ Hw^T + Hb); out = gate*elu(g_att) + (1-gate)*feat
// ---------------------------------------------------------------------------
__device__ __forceinline__ float blend_one(float accv, float hb, float att, float f) {
    float gt = 1.f / (1.f + __expf(-(accv + hb)));
    float fo = att > 0.f ? att : (__expf(att) - 1.f);
    return gt * fo + (1.f - gt) * f;
}

__global__ __launch_bounds__(256) void gemm2_tc_kernel(const float* __restrict__ feat,
                                                       const float* __restrict__ Hb,
                                                       float* __restrict__ out) {
    extern __shared__ char sm[];
    const int m0 = blockIdx.y << 7;
    const int n0 = blockIdx.x << 7;
    float acc[2][8][4];
#pragma unroll
    for (int mf = 0; mf < 2; ++mf)
#pragma unroll
        for (int nf = 0; nf < 8; ++nf)
#pragma unroll
            for (int q = 0; q < 4; ++q) acc[mf][nf][q] = 0.f;

    hmma_mainloop(acc, g_fh, g_fl, g_w2h, g_w2l, m0, n0, sm);

    const int warp = threadIdx.x >> 5, lane = threadIdx.x & 31;
    const int wm = warp & 3, wn = warp >> 2;
    const int g = lane >> 2, t = lane & 3;
#pragma unroll
    for (int mf = 0; mf < 2; ++mf)
#pragma unroll
        for (int nf = 0; nf < 8; ++nf) {
            const int m = m0 + wm * 32 + mf * 16 + g;
            const int n = n0 + wn * 64 + nf * 8 + 2 * t;
            float2 hb = *(const float2*)(Hb + n);
#pragma unroll
            for (int rr = 0; rr < 2; ++rr) {
                const int mm = m + rr * 8;
                float2 av = *(const float2*)(g_att + (size_t)mm * D_ + n);
                float2 fv = *(const float2*)(feat + (size_t)mm * D_ + n);
                float2 ov;
                ov.x = blend_one(acc[mf][nf][rr * 2 + 0], hb.x, av.x, fv.x);
                ov.y = blend_one(acc[mf][nf][rr * 2 + 1], hb.y, av.y, fv.y);
                *(float2*)(out + (size_t)mm * D_ + n) = ov;
            }
        }
}

// ---------------------------------------------------------------------------
// src/dst: warp per (b,a,i) row: tanh(h) . w_src / w_dst
// ---------------------------------------------------------------------------
__global__ void srcdst_kernel(const float* __restrict__ wsrc, const float* __restrict__ wdst) {
    const int warp = (blockIdx.x * blockDim.x + threadIdx.x) >> 5;
    const int lane = threadIdx.x & 31;
    const int a = (warp >> 9) % A_;
    const float* hr = g_h + (size_t)warp * E_;
    float t0 = tanhf(hr[lane]);
    float t1 = tanhf(hr[lane + 32]);
    float s = t0 * __ldg(wsrc + a * E_ + lane) + t1 * __ldg(wsrc + a * E_ + lane + 32);
    float d = t0 * __ldg(wdst + a * E_ + lane) + t1 * __ldg(wdst + a * E_ + lane + 32);
#pragma unroll
    for (int o = 16; o; o >>= 1) {
        s += __shfl_xor_sync(0xffffffffu, s, o);
        d += __shfl_xor_sync(0xffffffffu, d, o);
    }
    if (lane == 0) { g_src[warp] = s; g_dst[warp] = d; }
}

// ---------------------------------------------------------------------------
// Attention (HMMA): block = (itile of 128, a, b), 8 warps.
// Phase A: h[b,a] -> transposed bf16 hi/lo HT[e][j] in smem.
// Phase B: warp-per-row softmax stats (max, 1/sum) + packed mask bits.
// Phase C: 8 chunks of 64 j: recompute P -> bf16 hi/lo tile, then
//          HMMA  Ph@Hh + Pl@Hh + Ph@Hl  (fp32 accum).
// ---------------------------------------------------------------------------
#define HT_ROWB 1040             // 512 bf16 + 8 pad
#define P_ROWB 144               // 64 bf16 + 8 pad
#define OFF_HTH 0
#define OFF_HTL 66560
#define OFF_PBH 133120
#define OFF_PBL 151552
#define OFF_SRC 169984
#define OFF_DST 170496
#define OFF_RMX 172544
#define OFF_RIV 173056
#define OFF_MS  173568
#define ATT_SMEM_B (OFF_MS + 8192)   // 181760

__global__ __launch_bounds__(256) void attn_kernel(const void* __restrict__ adjv,
                                                   const float* __restrict__ bbias) {
    extern __shared__ char sm[];
    const uint32_t smu = smem_u32(sm);
    char* HTh = sm + OFF_HTH;
    char* HTl = sm + OFF_HTL;
    char* Pbh = sm + OFF_PBH;
    char* Pbl = sm + OFF_PBL;
    float* s_src = (float*)(sm + OFF_SRC);
    float* s_dst = (float*)(sm + OFF_DST);
    float* s_rmax = (float*)(sm + OFF_RMX);
    float* s_rinv = (float*)(sm + OFF_RIV);
    unsigned short* Ms = (unsigned short*)(sm + OFF_MS);   // [32 jwords][128 rows]

    const int tid = threadIdx.x;
    const int lane = tid & 31, warp = tid >> 5;
    const int b = blockIdx.z, a = blockIdx.y, it = blockIdx.x;
    const int ba = b * A_ + a;
    const int i0 = it * 128;

    // ---- Phase A: transpose + split h into HT; load vectors ----
    {
        const float4* hsrc = (const float4*)(g_h + (size_t)ba * N_ * E_);
        for (int v = tid; v < N_ * E_ / 4; v += 256) {
            float4 x = hsrc[v];
            const int j = v >> 4;
            const int e0 = (v & 15) << 2;
#pragma unroll
            for (int q = 0; q < 4; ++q) {
                __nv_bfloat16 hh, ll;
                split2((&x.x)[q], hh, ll);
                *(__nv_bfloat16*)(HTh + (e0 + q) * HT_ROWB + j * 2) = hh;
                *(__nv_bfloat16*)(HTl + (e0 + q) * HT_ROWB + j * 2) = ll;
            }
        }
        if (tid < 128) s_src[tid] = g_src[ba * N_ + i0 + tid];
        s_dst[tid] = g_dst[ba * N_ + tid];
        s_dst[tid + 256] = g_dst[ba * N_ + tid + 256];
    }
    __syncthreads();

    // ---- Phase B: stats (warp per row), packed mask bits ----
    const int adj_int = g_adj_int;
    for (int rr = warp; rr < 128; rr += 8) {
        const size_t rowoff = (size_t)(b * N_ + i0 + rr) * N_;
        unsigned mbits = 0;
        if (adj_int) {
            const uint4* ap = (const uint4*)((const int*)adjv + rowoff + lane * 16);
#pragma unroll
            for (int q = 0; q < 4; ++q) {
                uint4 w = ap[q];
                mbits |= (w.x ? 1u : 0u) << (q * 4 + 0);
                mbits |= (w.y ? 1u : 0u) << (q * 4 + 1);
                mbits |= (w.z ? 1u : 0u) << (q * 4 + 2);
                mbits |= (w.w ? 1u : 0u) << (q * 4 + 3);
            }
        } else {
            uint4 w = *(const uint4*)((const uint8_t*)adjv + rowoff + lane * 16);
            unsigned ws[4] = {w.x, w.y, w.z, w.w};
#pragma unroll
            for (int q = 0; q < 4; ++q)
#pragma unroll
                for (int bq = 0; bq < 4; ++bq)
                    mbits |= (((ws[q] >> (8 * bq)) & 0xffu) ? 1u : 0u) << (q * 4 + bq);
        }
        const float sbase = s_src[rr];
        alignas(16) float dv[16];
#pragma unroll
        for (int c = 0; c < 4; ++c)
            *(float4*)&dv[c * 4] = *(const float4*)&s_dst[lane * 16 + c * 4];
        float l[16];
        float mx = -1e30f;
#pragma unroll
        for (int q = 0; q < 16; ++q) {
            float v = sbase + dv[q];
            v = v >= 0.f ? v : 0.2f * v;
            l[q] = ((mbits >> q) & 1u) ? v : -999.f;
            mx = fmaxf(mx, l[q]);
        }
#pragma unroll
        for (int o = 16; o; o >>= 1) mx = fmaxf(mx, __shfl_xor_sync(0xffffffffu, mx, o));
        float ssum = 0.f;
#pragma unroll
        for (int q = 0; q < 16; ++q) ssum += __expf(l[q] - mx);
#pragma unroll
        for (int o = 16; o; o >>= 1) ssum += __shfl_xor_sync(0xffffffffu, ssum, o);
        if (lane == 0) {
            s_rmax[rr] = mx;
            s_rinv[rr] = __fdividef(1.f, ssum);
        }
        Ms[lane * 128 + rr] = (unsigned short)mbits;   // Ms[jword][row]
    }
    __syncthreads();

    // ---- Phase C: P tiles + HMMA ----
    const int wm = warp & 3, wn = warp >> 2;
    const int r = tid >> 1, jseg = (tid & 1) * 32;
    const float srcv = s_src[r], rmaxv = s_rmax[r], rinvv = s_rinv[r];

    const int arow = (lane & 7) + ((lane >> 3) & 1) * 8;
    const int acolb = (lane >> 4) * 16;
    const int brow = (lane & 7) + (lane >> 4) * 8;
    const int bcolb = ((lane >> 3) & 1) * 16;
    const uint32_t aP0 = smu + OFF_PBH + (uint32_t)(wm * 32 + arow) * P_ROWB + acolb;
    const uint32_t bH0 = smu + OFF_HTH + (uint32_t)(wn * 32 + brow) * HT_ROWB + bcolb;

    float acc[2][4][4];
#pragma unroll
    for (int mf = 0; mf < 2; ++mf)
#pragma unroll
        for (int nf = 0; nf < 4; ++nf)
#pragma unroll
            for (int q = 0; q < 4; ++q) acc[mf][nf][q] = 0.f;

    for (int jc = 0; jc < 8; ++jc) {
        const int j0 = jc * 64;
        // compute P chunk: this thread covers row r, j in [j0+jseg, j0+jseg+32)
        {
            const int jb = j0 + jseg;
            uint32_t mw0 = Ms[(jb >> 4) * 128 + r];
            uint32_t mw1 = Ms[((jb >> 4) + 1) * 128 + r];
            uint32_t mbits = mw0 | (mw1 << 16);
#pragma unroll
            for (int q = 0; q < 32; q += 2) {
                float d0 = s_dst[jb + q];
                float d1 = s_dst[jb + q + 1];
                float l0 = srcv + d0; l0 = l0 >= 0.f ? l0 : 0.2f * l0;
                float l1 = srcv + d1; l1 = l1 >= 0.f ? l1 : 0.2f * l1;
                if (!((mbits >> q) & 1u)) l0 = -999.f;
                if (!((mbits >> (q + 1)) & 1u)) l1 = -999.f;
                float p0 = __expf(l0 - rmaxv) * rinvv;
                float p1 = __expf(l1 - rmaxv) * rinvv;
                __nv_bfloat16 h0, lo0, h1, lo1;
                split2(p0, h0, lo0);
                split2(p1, h1, lo1);
                *(__nv_bfloat162*)(Pbh + r * P_ROWB + (jseg + q) * 2) = __nv_bfloat162(h0, h1);
                *(__nv_bfloat162*)(Pbl + r * P_ROWB + (jseg + q) * 2) = __nv_bfloat162(lo0, lo1);
            }
        }
        __syncthreads();
        // HMMA over this chunk (K=64 -> 4 k16 steps)
#pragma unroll
        for (int ks = 0; ks < 4; ++ks) {
            uint32_t ah[2][4], al[2][4], bh[2][4], bl[2][4];
#pragma unroll
            for (int mf = 0; mf < 2; ++mf) {
                ldsm_x4(ah[mf], aP0 + mf * 16 * P_ROWB + ks * 32);
                ldsm_x4(al[mf], aP0 + (OFF_PBL - OFF_PBH) + mf * 16 * P_ROWB + ks * 32);
            }
#pragma unroll
            for (int nfp = 0; nfp < 2; ++nfp) {
                ldsm_x4(bh[nfp], bH0 + nfp * 16 * HT_ROWB + j0 * 2 + ks * 32);
                ldsm_x4(bl[nfp], bH0 + (OFF_HTL - OFF_HTH) + nfp * 16 * HT_ROWB + j0 * 2 + ks * 32);
            }
#pragma unroll
            for (int nfp = 0; nfp < 2; ++nfp)
#pragma unroll
                for (int hf = 0; hf < 2; ++hf) {
                    const int nf = nfp * 2 + hf;
                    const uint32_t b0h = bh[nfp][hf * 2], b1h = bh[nfp][hf * 2 + 1];
                    const uint32_t b0l = bl[nfp][hf * 2], b1l = bl[nfp][hf * 2 + 1];
#pragma unroll
                    for (int mf = 0; mf < 2; ++mf) {
                        mma16816(acc[mf][nf], ah[mf][0], ah[mf][1], ah[mf][2], ah[mf][3], b0h, b1h);
                        mma16816(acc[mf][nf], al[mf][0], al[mf][1], al[mf][2], al[mf][3], b0h, b1h);
                        mma16816(acc[mf][nf], ah[mf][0], ah[mf][1], ah[mf][2], ah[mf][3], b0l, b1l);
                    }
                }
        }
        __syncthreads();
    }

    // ---- epilogue: bias + store to g_att ----
    const int g = lane >> 2, t = lane & 3;
#pragma unroll
    for (int mf = 0; mf < 2; ++mf)
#pragma unroll
        for (int nf = 0; nf < 4; ++nf) {
            const int row = i0 + wm * 32 + mf * 16 + g;
            const int col = wn * 32 + nf * 8 + 2 * t;
            float2 bias = *(const float2*)(bbias + col);
            float2 v0 = make_float2(acc[mf][nf][0] + bias.x, acc[mf][nf][1] + bias.y);
            float2 v1 = make_float2(acc[mf][nf][2] + bias.x, acc[mf][nf][3] + bias.y);
            *(float2*)&g_att[(size_t)(b * N_ + row) * D_ + a * E_ + col] = v0;
            *(float2*)&g_att[(size_t)(b * N_ + row + 8) * D_ + a * E_ + col] = v1;
        }
}

// ---------------------------------------------------------------------------
extern "C" void kernel_launch(void* const* d_in, const int* in_sizes, int n_in,
                              void* d_out, int out_size) {
    const float* feat = (const float*)d_in[0];
    const void* adj = d_in[1];
    const float* W = (const float*)d_in[2];
    const float* bbias = (const float*)d_in[3];
    const float* wsrc = (const float*)d_in[4];
    const float* wdst = (const float*)d_in[5];
    const float* Hw = (const float*)d_in[6];
    const float* Hb = (const float*)d_in[7];
    float* out = (float*)d_out;

    detect_adj_kernel<<<1, 32>>>((const int*)adj);
    conv_feat_kernel<<<M_ * D_ / 1024, 256>>>(feat);
    conv_w1_kernel<<<D_, 256>>>(W);
    conv_w2_kernel<<<D_ * D_ / 1024, 256>>>(Hw);

    cudaFuncSetAttribute(gemm1_tc_kernel, cudaFuncAttributeMaxDynamicSharedMemorySize, GEMM_SMEM);
    cudaFuncSetAttribute(gemm2_tc_kernel, cudaFuncAttributeMaxDynamicSharedMemorySize, GEMM_SMEM);
    cudaFuncSetAttribute(attn_kernel, cudaFuncAttributeMaxDynamicSharedMemorySize, ATT_SMEM_B);

    gemm1_tc_kernel<<<dim3(D_ / 128, M_ / 128), 256, GEMM_SMEM>>>();
    srcdst_kernel<<<(B_ * A_ * N_) / 8, 256>>>(wsrc, wdst);

    attn_kernel<<<dim3(N_ / 128, A_, B_), 256, ATT_SMEM_B>>>(adj, bbias);

    gemm2_tc_kernel<<<dim3(D_ / 128, M_ / 128), 256, GEMM_SMEM>>>(feat, Hb, out);
}